// round 1
// baseline (speedup 1.0000x reference)
#include <cuda_runtime.h>

// Problem constants
#define NB 4          // batch
#define NC 128        // channels
#define NH 4          // heads
#define ND 32         // head dim
#define NS 4096       // spatial (64*64)
#define GN_EPS 1e-5f

// q pre-scale: (1/sqrt(32)) * log2(e)  -> softmax done in base-2 domain
#define QSCALE 0.25501817097393111f

// ---------------- scratch (static device allocations, allowed) -------------
__device__ __align__(16) float g_q[NB * NH * NS * ND];   // [b][h][n][d]  8MB
__device__ __align__(16) float g_k[NB * NH * NS * ND];   // 8MB
__device__ __align__(16) float g_v[NB * NH * NS * ND];   // 8MB
__device__ __align__(16) float g_ao[NB * NC * NS];       // attn out [b][c][n] 8MB
__device__ __align__(16) float g_y[NB * NC * NS];        // proj out [b][c][n] 8MB
__device__ float2 g_part[NB * 2 * 64 * 2];               // per-block GN partials
__device__ float2 g_stats[NB * 4];                       // (mean, rstd) per (b,g)

// ===========================================================================
// Kernel 1: QKV projection.  qkv[b,o,n] = sum_c W[o,c] * x[b,c,n]
// grid (4096/64, 384/64, B), 256 threads, each thread 4x4 outputs.
// Q rows get pre-scaled by QSCALE.
// ===========================================================================
__global__ __launch_bounds__(256) void qkv_kernel(const float* __restrict__ x,
                                                  const float* __restrict__ w) {
    __shared__ __align__(16) float Wt[128][64];  // [c][m]
    __shared__ __align__(16) float Xs[128][64];  // [c][n]
    const int b = blockIdx.z;
    const int n0 = blockIdx.x * 64;
    const int m0 = blockIdx.y * 64;
    const int tid = threadIdx.x;

    // load W tile transposed: W[m0+m][c] -> Wt[c][m]
    for (int idx = tid; idx < 64 * 32; idx += 256) {
        int m = idx >> 5, c4 = idx & 31;
        float4 wv = *(const float4*)&w[(m0 + m) * 128 + c4 * 4];
        Wt[c4 * 4 + 0][m] = wv.x;
        Wt[c4 * 4 + 1][m] = wv.y;
        Wt[c4 * 4 + 2][m] = wv.z;
        Wt[c4 * 4 + 3][m] = wv.w;
    }
    // load X tile: x[b][r][n0..n0+63]
    for (int idx = tid; idx < 128 * 16; idx += 256) {
        int r = idx >> 4, c4 = idx & 15;
        *(float4*)&Xs[r][c4 * 4] =
            *(const float4*)&x[(b * 128 + r) * 4096 + n0 + c4 * 4];
    }
    __syncthreads();

    const int tx = tid & 15, ty = tid >> 4;
    float acc[4][4];
#pragma unroll
    for (int i = 0; i < 4; i++)
#pragma unroll
        for (int j = 0; j < 4; j++) acc[i][j] = 0.f;

#pragma unroll 4
    for (int k = 0; k < 128; k++) {
        float4 wv = *(float4*)&Wt[k][ty * 4];
        float4 xv = *(float4*)&Xs[k][tx * 4];
        acc[0][0] = fmaf(wv.x, xv.x, acc[0][0]);
        acc[0][1] = fmaf(wv.x, xv.y, acc[0][1]);
        acc[0][2] = fmaf(wv.x, xv.z, acc[0][2]);
        acc[0][3] = fmaf(wv.x, xv.w, acc[0][3]);
        acc[1][0] = fmaf(wv.y, xv.x, acc[1][0]);
        acc[1][1] = fmaf(wv.y, xv.y, acc[1][1]);
        acc[1][2] = fmaf(wv.y, xv.z, acc[1][2]);
        acc[1][3] = fmaf(wv.y, xv.w, acc[1][3]);
        acc[2][0] = fmaf(wv.z, xv.x, acc[2][0]);
        acc[2][1] = fmaf(wv.z, xv.y, acc[2][1]);
        acc[2][2] = fmaf(wv.z, xv.z, acc[2][2]);
        acc[2][3] = fmaf(wv.z, xv.w, acc[2][3]);
        acc[3][0] = fmaf(wv.w, xv.x, acc[3][0]);
        acc[3][1] = fmaf(wv.w, xv.y, acc[3][1]);
        acc[3][2] = fmaf(wv.w, xv.z, acc[3][2]);
        acc[3][3] = fmaf(wv.w, xv.w, acc[3][3]);
    }

    const int oc0 = m0 + ty * 4;             // 4 consecutive out channels
    const int which = oc0 >> 7;              // 0=q 1=k 2=v
    const int h = (oc0 >> 5) & 3;
    const int di0 = oc0 & 31;                // multiple of 4
    float* dst = (which == 0) ? g_q : ((which == 1) ? g_k : g_v);
    const float sc = (which == 0) ? QSCALE : 1.0f;
    const long base = ((long)(b * 4 + h) * 4096) * 32;
#pragma unroll
    for (int j = 0; j < 4; j++) {
        int n = n0 + tx * 4 + j;
        float4 v = make_float4(acc[0][j] * sc, acc[1][j] * sc,
                               acc[2][j] * sc, acc[3][j] * sc);
        *(float4*)&dst[base + (long)n * 32 + di0] = v;
    }
}

// ===========================================================================
// Kernel 2: flash attention.  grid (4096/128, H, B), 128 threads.
// One query per thread; KV tiles of 64 rows in SMEM; online softmax in base-2.
// Writes attention output transposed to [b][c][n] (coalesced along n).
// ===========================================================================
__global__ __launch_bounds__(128, 4) void attn_kernel() {
    __shared__ __align__(16) float Ks[64 * 32];
    __shared__ __align__(16) float Vs[64 * 32];
    const int b = blockIdx.z, h = blockIdx.y;
    const int qi = blockIdx.x * 128 + threadIdx.x;

    const float* qp = &g_q[((long)(b * 4 + h) * 4096 + qi) * 32];
    float q[32];
#pragma unroll
    for (int u = 0; u < 8; u++) {
        float4 t = *(const float4*)&qp[u * 4];
        q[4 * u + 0] = t.x; q[4 * u + 1] = t.y;
        q[4 * u + 2] = t.z; q[4 * u + 3] = t.w;
    }
    float o[32];
#pragma unroll
    for (int i = 0; i < 32; i++) o[i] = 0.f;
    float m = -1e30f, l = 0.f;

    const float4* kb = (const float4*)&g_k[(long)(b * 4 + h) * 4096 * 32];
    const float4* vb = (const float4*)&g_v[(long)(b * 4 + h) * 4096 * 32];

    for (int t0 = 0; t0 < 4096; t0 += 64) {
        const float4* ksrc = kb + t0 * 8;
        const float4* vsrc = vb + t0 * 8;
        for (int i = threadIdx.x; i < 512; i += 128) {
            ((float4*)Ks)[i] = ksrc[i];
            ((float4*)Vs)[i] = vsrc[i];
        }
        __syncthreads();

#pragma unroll 1
        for (int j = 0; j < 64; j++) {
            const float4* kr = (const float4*)&Ks[j * 32];
            float sa0 = 0.f, sa1 = 0.f, sa2 = 0.f, sa3 = 0.f;
#pragma unroll
            for (int u = 0; u < 8; u += 4) {
                float4 k0 = kr[u + 0], k1 = kr[u + 1], k2 = kr[u + 2], k3 = kr[u + 3];
                sa0 = fmaf(q[4*(u+0)+0], k0.x, fmaf(q[4*(u+0)+1], k0.y,
                      fmaf(q[4*(u+0)+2], k0.z, fmaf(q[4*(u+0)+3], k0.w, sa0))));
                sa1 = fmaf(q[4*(u+1)+0], k1.x, fmaf(q[4*(u+1)+1], k1.y,
                      fmaf(q[4*(u+1)+2], k1.z, fmaf(q[4*(u+1)+3], k1.w, sa1))));
                sa2 = fmaf(q[4*(u+2)+0], k2.x, fmaf(q[4*(u+2)+1], k2.y,
                      fmaf(q[4*(u+2)+2], k2.z, fmaf(q[4*(u+2)+3], k2.w, sa2))));
                sa3 = fmaf(q[4*(u+3)+0], k3.x, fmaf(q[4*(u+3)+1], k3.y,
                      fmaf(q[4*(u+3)+2], k3.z, fmaf(q[4*(u+3)+3], k3.w, sa3))));
            }
            float s = (sa0 + sa1) + (sa2 + sa3);  // already in log2-units

            float p;
            if (s > m) {  // new running max — rare (~record statistics)
                float corr = exp2f(m - s);
                l *= corr;
#pragma unroll
                for (int i = 0; i < 32; i++) o[i] *= corr;
                m = s;
                p = 1.f;
            } else {
                p = exp2f(s - m);
            }
            l += p;

            const float4* vr = (const float4*)&Vs[j * 32];
#pragma unroll
            for (int u = 0; u < 8; u++) {
                float4 vv = vr[u];
                o[4 * u + 0] = fmaf(p, vv.x, o[4 * u + 0]);
                o[4 * u + 1] = fmaf(p, vv.y, o[4 * u + 1]);
                o[4 * u + 2] = fmaf(p, vv.z, o[4 * u + 2]);
                o[4 * u + 3] = fmaf(p, vv.w, o[4 * u + 3]);
            }
        }
        __syncthreads();
    }

    const float inv = 1.f / l;
    float* op = &g_ao[(long)(b * 128 + h * 32) * 4096 + qi];
#pragma unroll
    for (int i = 0; i < 32; i++) op[i * 4096] = o[i] * inv;  // coalesced over qi
}

// ===========================================================================
// Kernel 3: output projection + bias, plus per-(b,group) partial sums for GN.
// grid (4096/64, 128/64, B), 256 threads.
// ===========================================================================
__global__ __launch_bounds__(256) void proj_kernel(const float* __restrict__ w,
                                                   const float* __restrict__ bias) {
    __shared__ __align__(16) float Wt[128][64];
    __shared__ __align__(16) float Xs[128][64];
    __shared__ float wred[8][2];
    const int b = blockIdx.z;
    const int n0 = blockIdx.x * 64;
    const int m0 = blockIdx.y * 64;
    const int tid = threadIdx.x;

    for (int idx = tid; idx < 64 * 32; idx += 256) {
        int mm = idx >> 5, c4 = idx & 31;
        float4 wv = *(const float4*)&w[(m0 + mm) * 128 + c4 * 4];
        Wt[c4 * 4 + 0][mm] = wv.x;
        Wt[c4 * 4 + 1][mm] = wv.y;
        Wt[c4 * 4 + 2][mm] = wv.z;
        Wt[c4 * 4 + 3][mm] = wv.w;
    }
    for (int idx = tid; idx < 128 * 16; idx += 256) {
        int r = idx >> 4, c4 = idx & 15;
        *(float4*)&Xs[r][c4 * 4] =
            *(const float4*)&g_ao[(long)(b * 128 + r) * 4096 + n0 + c4 * 4];
    }
    __syncthreads();

    const int tx = tid & 15, ty = tid >> 4;
    float acc[4][4];
#pragma unroll
    for (int i = 0; i < 4; i++)
#pragma unroll
        for (int j = 0; j < 4; j++) acc[i][j] = 0.f;

#pragma unroll 4
    for (int k = 0; k < 128; k++) {
        float4 wv = *(float4*)&Wt[k][ty * 4];
        float4 xv = *(float4*)&Xs[k][tx * 4];
        acc[0][0] = fmaf(wv.x, xv.x, acc[0][0]);
        acc[0][1] = fmaf(wv.x, xv.y, acc[0][1]);
        acc[0][2] = fmaf(wv.x, xv.z, acc[0][2]);
        acc[0][3] = fmaf(wv.x, xv.w, acc[0][3]);
        acc[1][0] = fmaf(wv.y, xv.x, acc[1][0]);
        acc[1][1] = fmaf(wv.y, xv.y, acc[1][1]);
        acc[1][2] = fmaf(wv.y, xv.z, acc[1][2]);
        acc[1][3] = fmaf(wv.y, xv.w, acc[1][3]);
        acc[2][0] = fmaf(wv.z, xv.x, acc[2][0]);
        acc[2][1] = fmaf(wv.z, xv.y, acc[2][1]);
        acc[2][2] = fmaf(wv.z, xv.z, acc[2][2]);
        acc[2][3] = fmaf(wv.z, xv.w, acc[2][3]);
        acc[3][0] = fmaf(wv.w, xv.x, acc[3][0]);
        acc[3][1] = fmaf(wv.w, xv.y, acc[3][1]);
        acc[3][2] = fmaf(wv.w, xv.z, acc[3][2]);
        acc[3][3] = fmaf(wv.w, xv.w, acc[3][3]);
    }

    const int co0 = m0 + ty * 4;
    float lsum = 0.f, lsq = 0.f;
#pragma unroll
    for (int mm = 0; mm < 4; mm++) {
        float bv = bias[co0 + mm];
#pragma unroll
        for (int j = 0; j < 4; j++) {
            float v = acc[mm][j] + bv;
            acc[mm][j] = v;
            lsum += v;
            lsq = fmaf(v, v, lsq);
        }
        *(float4*)&g_y[(long)(b * 128 + co0 + mm) * 4096 + n0 + tx * 4] =
            make_float4(acc[mm][0], acc[mm][1], acc[mm][2], acc[mm][3]);
    }

    // block-level GN partials: all 4 channels of a thread are in one group;
    // warps 0-3 -> group_local 0, warps 4-7 -> group_local 1
#pragma unroll
    for (int off = 16; off > 0; off >>= 1) {
        lsum += __shfl_xor_sync(0xffffffffu, lsum, off);
        lsq  += __shfl_xor_sync(0xffffffffu, lsq, off);
    }
    const int wid = tid >> 5, lane = tid & 31;
    if (lane == 0) { wred[wid][0] = lsum; wred[wid][1] = lsq; }
    __syncthreads();
    if (tid == 0) {
        float s0 = 0.f, q0 = 0.f, s1 = 0.f, q1 = 0.f;
#pragma unroll
        for (int ww = 0; ww < 4; ww++) { s0 += wred[ww][0]; q0 += wred[ww][1]; }
#pragma unroll
        for (int ww = 4; ww < 8; ww++) { s1 += wred[ww][0]; q1 += wred[ww][1]; }
        const int bx = blockIdx.x, by = blockIdx.y;
        g_part[((b * 2 + by) * 64 + bx) * 2 + 0] = make_float2(s0, q0);
        g_part[((b * 2 + by) * 64 + bx) * 2 + 1] = make_float2(s1, q1);
    }
}

// ===========================================================================
// Kernel 3b: reduce partials to (mean, rstd) per (b, group). grid (4,4), 64thr
// ===========================================================================
__global__ void stats_kernel() {
    const int g = blockIdx.x, b = blockIdx.y;
    const int by = g >> 1, gl = g & 1;
    const int t = threadIdx.x;  // 64
    float2 pv = g_part[((b * 2 + by) * 64 + t) * 2 + gl];
    float s = pv.x, ss = pv.y;
#pragma unroll
    for (int off = 16; off > 0; off >>= 1) {
        s  += __shfl_xor_sync(0xffffffffu, s, off);
        ss += __shfl_xor_sync(0xffffffffu, ss, off);
    }
    __shared__ float2 w2[2];
    if ((t & 31) == 0) w2[t >> 5] = make_float2(s, ss);
    __syncthreads();
    if (t == 0) {
        s = w2[0].x + w2[1].x;
        ss = w2[0].y + w2[1].y;
        const float invn = 1.f / 131072.f;  // 32 channels * 4096 pixels
        float mean = s * invn;
        float var = ss * invn - mean * mean;
        g_stats[b * 4 + g] = make_float2(mean, rsqrtf(var + GN_EPS));
    }
}

// ===========================================================================
// Kernel 4: GroupNorm affine + residual.  elementwise, float4.
// ===========================================================================
__global__ __launch_bounds__(256) void norm_kernel(const float* __restrict__ x,
                                                   const float* __restrict__ gamma,
                                                   const float* __restrict__ beta,
                                                   float* __restrict__ out) {
    const int i4 = blockIdx.x * 256 + threadIdx.x;  // 524288 float4s
    const int e = i4 * 4;
    const int c = (e >> 12) & 127;
    const int b = e >> 19;
    float2 st = g_stats[b * 4 + (c >> 5)];
    float ga = gamma[c] * st.y;
    float be = beta[c] - st.x * ga;
    float4 yv = *(const float4*)&g_y[e];
    float4 xv = *(const float4*)&x[e];
    float4 r;
    r.x = fmaf(yv.x, ga, be) + xv.x;
    r.y = fmaf(yv.y, ga, be) + xv.y;
    r.z = fmaf(yv.z, ga, be) + xv.z;
    r.w = fmaf(yv.w, ga, be) + xv.w;
    *(float4*)&out[e] = r;
}

// ===========================================================================
extern "C" void kernel_launch(void* const* d_in, const int* in_sizes, int n_in,
                              void* d_out, int out_size) {
    const float* x      = (const float*)d_in[0];
    const float* w_qkv  = (const float*)d_in[1];
    const float* w_out  = (const float*)d_in[2];
    const float* b_out  = (const float*)d_in[3];
    const float* gammap = (const float*)d_in[4];
    const float* betap  = (const float*)d_in[5];
    float* out = (float*)d_out;

    qkv_kernel<<<dim3(64, 6, 4), 256>>>(x, w_qkv);
    attn_kernel<<<dim3(32, 4, 4), 128>>>();
    proj_kernel<<<dim3(64, 2, 4), 256>>>(w_out, b_out);
    stats_kernel<<<dim3(4, 4), 64>>>();
    norm_kernel<<<2048, 256>>>(x, gammap, betap, out);
}

// round 3
// speedup vs baseline: 4.6780x; 4.6780x over previous
#include <cuda_runtime.h>
#include <cuda_fp16.h>

typedef unsigned int u32;

#define GN_EPS 1e-5f
// (1/sqrt(32)) * log2(e): softmax runs in base-2 domain
#define QSCALE 0.25501817097393111f

// ---------------- scratch (static device allocations, allowed) -------------
__device__ __align__(16) __half g_qh[4 * 4 * 4096 * 32];  // [b][h][n][d] 4MB
__device__ __align__(16) __half g_kh[4 * 4 * 4096 * 32];
__device__ __align__(16) __half g_vh[4 * 4 * 4096 * 32];
__device__ __align__(16) float g_ao[4 * 128 * 4096];      // attn out [b][c][n]
__device__ __align__(16) float g_y[4 * 128 * 4096];       // proj out [b][c][n]
__device__ float2 g_part[4 * 2 * 64 * 2];
__device__ float2 g_stats[16];

// ---------------- PTX helpers ----------------------------------------------
__device__ __forceinline__ float ex2(float x) {
    float r; asm("ex2.approx.ftz.f32 %0, %1;" : "=f"(r) : "f"(x)); return r;
}
__device__ __forceinline__ void ldsm_x4(u32* r, u32 addr) {
    asm volatile("ldmatrix.sync.aligned.m8n8.x4.shared.b16 {%0,%1,%2,%3}, [%4];"
                 : "=r"(r[0]), "=r"(r[1]), "=r"(r[2]), "=r"(r[3]) : "r"(addr));
}
__device__ __forceinline__ void ldsm_x4_t(u32* r, u32 addr) {
    asm volatile("ldmatrix.sync.aligned.m8n8.x4.trans.shared.b16 {%0,%1,%2,%3}, [%4];"
                 : "=r"(r[0]), "=r"(r[1]), "=r"(r[2]), "=r"(r[3]) : "r"(addr));
}
__device__ __forceinline__ void mma16816(float* c, const u32* a, const u32* b) {
    asm volatile("mma.sync.aligned.m16n8k16.row.col.f32.f16.f16.f32 "
                 "{%0,%1,%2,%3}, {%4,%5,%6,%7}, {%8,%9}, {%0,%1,%2,%3};"
                 : "+f"(c[0]), "+f"(c[1]), "+f"(c[2]), "+f"(c[3])
                 : "r"(a[0]), "r"(a[1]), "r"(a[2]), "r"(a[3]), "r"(b[0]), "r"(b[1]));
}
__device__ __forceinline__ u32 packh2(float a, float b) {
    __half2 h = __floats2half2_rn(a, b);
    return *(u32*)&h;
}

// ===========================================================================
// Kernel 1: QKV projection (fp32 math), outputs fp16 Q(scaled)/K/V.
// grid (4096/64, 384/64, B), 256 threads, thread computes 4x4.
// ===========================================================================
__global__ __launch_bounds__(256) void qkv_kernel(const float* __restrict__ x,
                                                  const float* __restrict__ w) {
    __shared__ __align__(16) float Wt[128][64];
    __shared__ __align__(16) float Xs[128][64];
    const int b = blockIdx.z;
    const int n0 = blockIdx.x * 64;
    const int m0 = blockIdx.y * 64;
    const int tid = threadIdx.x;

    for (int idx = tid; idx < 64 * 32; idx += 256) {
        int mm = idx >> 5, c4 = idx & 31;
        float4 wv = *(const float4*)&w[(m0 + mm) * 128 + c4 * 4];
        Wt[c4 * 4 + 0][mm] = wv.x;
        Wt[c4 * 4 + 1][mm] = wv.y;
        Wt[c4 * 4 + 2][mm] = wv.z;
        Wt[c4 * 4 + 3][mm] = wv.w;
    }
    for (int idx = tid; idx < 128 * 16; idx += 256) {
        int r = idx >> 4, c4 = idx & 15;
        *(float4*)&Xs[r][c4 * 4] =
            *(const float4*)&x[(b * 128 + r) * 4096 + n0 + c4 * 4];
    }
    __syncthreads();

    const int tx = tid & 15, ty = tid >> 4;
    float acc[4][4];
#pragma unroll
    for (int i = 0; i < 4; i++)
#pragma unroll
        for (int j = 0; j < 4; j++) acc[i][j] = 0.f;

#pragma unroll 4
    for (int k = 0; k < 128; k++) {
        float4 wv = *(float4*)&Wt[k][ty * 4];
        float4 xv = *(float4*)&Xs[k][tx * 4];
        acc[0][0] = fmaf(wv.x, xv.x, acc[0][0]);
        acc[0][1] = fmaf(wv.x, xv.y, acc[0][1]);
        acc[0][2] = fmaf(wv.x, xv.z, acc[0][2]);
        acc[0][3] = fmaf(wv.x, xv.w, acc[0][3]);
        acc[1][0] = fmaf(wv.y, xv.x, acc[1][0]);
        acc[1][1] = fmaf(wv.y, xv.y, acc[1][1]);
        acc[1][2] = fmaf(wv.y, xv.z, acc[1][2]);
        acc[1][3] = fmaf(wv.y, xv.w, acc[1][3]);
        acc[2][0] = fmaf(wv.z, xv.x, acc[2][0]);
        acc[2][1] = fmaf(wv.z, xv.y, acc[2][1]);
        acc[2][2] = fmaf(wv.z, xv.z, acc[2][2]);
        acc[2][3] = fmaf(wv.z, xv.w, acc[2][3]);
        acc[3][0] = fmaf(wv.w, xv.x, acc[3][0]);
        acc[3][1] = fmaf(wv.w, xv.y, acc[3][1]);
        acc[3][2] = fmaf(wv.w, xv.z, acc[3][2]);
        acc[3][3] = fmaf(wv.w, xv.w, acc[3][3]);
    }

    const int oc0 = m0 + ty * 4;
    const int which = oc0 >> 7;              // 0=q 1=k 2=v
    const int hh = (oc0 >> 5) & 3;
    const int di0 = oc0 & 31;
    __half* dst = (which == 0) ? g_qh : ((which == 1) ? g_kh : g_vh);
    const float sc = (which == 0) ? QSCALE : 1.0f;
    const long base = ((long)(b * 4 + hh) * 4096) * 32;
#pragma unroll
    for (int j = 0; j < 4; j++) {
        int n = n0 + tx * 4 + j;
        __half2 p01 = __floats2half2_rn(acc[0][j] * sc, acc[1][j] * sc);
        __half2 p23 = __floats2half2_rn(acc[2][j] * sc, acc[3][j] * sc);
        *(__half2*)&dst[base + (long)n * 32 + di0] = p01;
        *(__half2*)&dst[base + (long)n * 32 + di0 + 2] = p23;
    }
}

// ===========================================================================
// Kernel 2: fp16 tensor-core flash attention.
// grid (4096/64, H, B), 128 threads (4 warps), 16 q-rows per warp.
// ===========================================================================
__global__ __launch_bounds__(128) void attn_kernel() {
    __shared__ __align__(16) __half Qs[64 * 40];   // padded rows: 40 halfs
    __shared__ __align__(16) __half Ks[64 * 40];
    __shared__ __align__(16) __half Vs[64 * 40];
    __shared__ __align__(16) float Os[64 * 33];

    const int b = blockIdx.z, hh = blockIdx.y;
    const int q0 = blockIdx.x * 64;
    const int tid = threadIdx.x;
    const int wrp = tid >> 5, lane = tid & 31;
    const long bh = (long)(b * 4 + hh) * 4096;

    // stage Q tile (64 x 32 halfs)
    {
        const uint4* qg = (const uint4*)&g_qh[(bh + q0) * 32];
        for (int i = tid; i < 256; i += 128) {
            int row = i >> 2, ch = i & 3;
            *(uint4*)&Qs[row * 40 + ch * 8] = qg[i];
        }
    }
    __syncthreads();

    // Q A-fragments for both k-steps (d 0-15, 16-31), held all kernel
    u32 qa[8];
    {
        int r = lane & 15, cc = lane >> 4;
        u32 a = (u32)__cvta_generic_to_shared(&Qs[(wrp * 16 + r) * 40 + cc * 8]);
        ldsm_x4(qa + 0, a);
        ldsm_x4(qa + 4, a + 32);  // +16 halfs
    }

    float o[4][4];
#pragma unroll
    for (int i = 0; i < 4; i++)
#pragma unroll
        for (int j = 0; j < 4; j++) o[i][j] = 0.f;
    float m0 = -1e30f, m1 = -1e30f, l0 = 0.f, l1 = 0.f;

    const uint4* kg = (const uint4*)&g_kh[bh * 32];
    const uint4* vg = (const uint4*)&g_vh[bh * 32];

    // precomputed ldmatrix lane addresses
    const u32 kaddr = (u32)__cvta_generic_to_shared(
        &Ks[(lane & 7) * 40 + (lane >> 3) * 8]);           // + nt*8 rows
    const int vm = lane >> 3;                               // 0..3
    const u32 vaddr = (u32)__cvta_generic_to_shared(
        &Vs[((vm & 1) * 8 + (lane & 7)) * 40 + (vm >> 1) * 8]);  // +kv*16 rows, +dh*16 cols

    for (int t0 = 0; t0 < 4096; t0 += 64) {
        const uint4* ksrc = kg + t0 * 4;
        const uint4* vsrc = vg + t0 * 4;
        for (int i = tid; i < 256; i += 128) {
            int row = i >> 2, ch = i & 3;
            *(uint4*)&Ks[row * 40 + ch * 8] = ksrc[i];
            *(uint4*)&Vs[row * 40 + ch * 8] = vsrc[i];
        }
        __syncthreads();

        // ---- S = Q K^T : 8 n-tiles x 2 k-steps
        float s[8][4];
#pragma unroll
        for (int nt = 0; nt < 8; nt++) {
            s[nt][0] = s[nt][1] = s[nt][2] = s[nt][3] = 0.f;
            u32 kb[4];
            ldsm_x4(kb, kaddr + nt * 8 * 80);   // 8 rows * 80 bytes
            mma16816(s[nt], qa + 0, kb + 0);
            mma16816(s[nt], qa + 4, kb + 2);
        }

        // ---- online softmax (base-2)
        float mx0 = -1e30f, mx1 = -1e30f;
#pragma unroll
        for (int nt = 0; nt < 8; nt++) {
            mx0 = fmaxf(mx0, fmaxf(s[nt][0], s[nt][1]));
            mx1 = fmaxf(mx1, fmaxf(s[nt][2], s[nt][3]));
        }
        mx0 = fmaxf(mx0, __shfl_xor_sync(0xffffffffu, mx0, 1));
        mx0 = fmaxf(mx0, __shfl_xor_sync(0xffffffffu, mx0, 2));
        mx1 = fmaxf(mx1, __shfl_xor_sync(0xffffffffu, mx1, 1));
        mx1 = fmaxf(mx1, __shfl_xor_sync(0xffffffffu, mx1, 2));
        float nm0 = fmaxf(m0, mx0), nm1 = fmaxf(m1, mx1);
        float corr0 = ex2(m0 - nm0), corr1 = ex2(m1 - nm1);
        m0 = nm0; m1 = nm1;

        u32 pa[8][2];
        float ls0 = 0.f, ls1 = 0.f;
#pragma unroll
        for (int nt = 0; nt < 8; nt++) {
            float p0 = ex2(s[nt][0] - m0);
            float p1 = ex2(s[nt][1] - m0);
            float p2 = ex2(s[nt][2] - m1);
            float p3 = ex2(s[nt][3] - m1);
            ls0 += p0 + p1; ls1 += p2 + p3;
            pa[nt][0] = packh2(p0, p1);
            pa[nt][1] = packh2(p2, p3);
        }
        l0 = l0 * corr0 + ls0;
        l1 = l1 * corr1 + ls1;
#pragma unroll
        for (int nd = 0; nd < 4; nd++) {
            o[nd][0] *= corr0; o[nd][1] *= corr0;
            o[nd][2] *= corr1; o[nd][3] *= corr1;
        }

        // ---- O += P V : 4 k-steps (16 keys each) x 2 d-halves
#pragma unroll
        for (int kv = 0; kv < 4; kv++) {
            u32 A[4] = {pa[2 * kv][0], pa[2 * kv][1],
                        pa[2 * kv + 1][0], pa[2 * kv + 1][1]};
#pragma unroll
            for (int dh = 0; dh < 2; dh++) {
                u32 vb[4];
                ldsm_x4_t(vb, vaddr + kv * 16 * 80 + dh * 32);
                mma16816(o[2 * dh + 0], A, vb + 0);
                mma16816(o[2 * dh + 1], A, vb + 2);
            }
        }
        __syncthreads();
    }

    // ---- epilogue: normalize, stage to SMEM, coalesced global write
    l0 += __shfl_xor_sync(0xffffffffu, l0, 1);
    l0 += __shfl_xor_sync(0xffffffffu, l0, 2);
    l1 += __shfl_xor_sync(0xffffffffu, l1, 1);
    l1 += __shfl_xor_sync(0xffffffffu, l1, 2);
    const float inv0 = 1.f / l0, inv1 = 1.f / l1;
    const int grp = lane >> 2, t4 = lane & 3;
#pragma unroll
    for (int nd = 0; nd < 4; nd++) {
        Os[(wrp * 16 + grp) * 33 + nd * 8 + 2 * t4 + 0] = o[nd][0] * inv0;
        Os[(wrp * 16 + grp) * 33 + nd * 8 + 2 * t4 + 1] = o[nd][1] * inv0;
        Os[(wrp * 16 + grp + 8) * 33 + nd * 8 + 2 * t4 + 0] = o[nd][2] * inv1;
        Os[(wrp * 16 + grp + 8) * 33 + nd * 8 + 2 * t4 + 1] = o[nd][3] * inv1;
    }
    __syncthreads();

    float* ob = &g_ao[(long)(b * 128 + hh * 32) * 4096 + q0];
    const int dd = tid >> 2, seg = tid & 3;
#pragma unroll
    for (int i = 0; i < 16; i += 4) {
        float4 vv;
        vv.x = Os[(seg * 16 + i + 0) * 33 + dd];
        vv.y = Os[(seg * 16 + i + 1) * 33 + dd];
        vv.z = Os[(seg * 16 + i + 2) * 33 + dd];
        vv.w = Os[(seg * 16 + i + 3) * 33 + dd];
        *(float4*)&ob[dd * 4096 + seg * 16 + i] = vv;
    }
}

// ===========================================================================
// Kernel 3: output projection + bias + GN partials (fp32).
// ===========================================================================
__global__ __launch_bounds__(256) void proj_kernel(const float* __restrict__ w,
                                                   const float* __restrict__ bias) {
    __shared__ __align__(16) float Wt[128][64];
    __shared__ __align__(16) float Xs[128][64];
    __shared__ float wred[8][2];
    const int b = blockIdx.z;
    const int n0 = blockIdx.x * 64;
    const int m0 = blockIdx.y * 64;
    const int tid = threadIdx.x;

    for (int idx = tid; idx < 64 * 32; idx += 256) {
        int mm = idx >> 5, c4 = idx & 31;
        float4 wv = *(const float4*)&w[(m0 + mm) * 128 + c4 * 4];
        Wt[c4 * 4 + 0][mm] = wv.x;
        Wt[c4 * 4 + 1][mm] = wv.y;
        Wt[c4 * 4 + 2][mm] = wv.z;
        Wt[c4 * 4 + 3][mm] = wv.w;
    }
    for (int idx = tid; idx < 128 * 16; idx += 256) {
        int r = idx >> 4, c4 = idx & 15;
        *(float4*)&Xs[r][c4 * 4] =
            *(const float4*)&g_ao[(long)(b * 128 + r) * 4096 + n0 + c4 * 4];
    }
    __syncthreads();

    const int tx = tid & 15, ty = tid >> 4;
    float acc[4][4];
#pragma unroll
    for (int i = 0; i < 4; i++)
#pragma unroll
        for (int j = 0; j < 4; j++) acc[i][j] = 0.f;

#pragma unroll 4
    for (int k = 0; k < 128; k++) {
        float4 wv = *(float4*)&Wt[k][ty * 4];
        float4 xv = *(float4*)&Xs[k][tx * 4];
        acc[0][0] = fmaf(wv.x, xv.x, acc[0][0]);
        acc[0][1] = fmaf(wv.x, xv.y, acc[0][1]);
        acc[0][2] = fmaf(wv.x, xv.z, acc[0][2]);
        acc[0][3] = fmaf(wv.x, xv.w, acc[0][3]);
        acc[1][0] = fmaf(wv.y, xv.x, acc[1][0]);
        acc[1][1] = fmaf(wv.y, xv.y, acc[1][1]);
        acc[1][2] = fmaf(wv.y, xv.z, acc[1][2]);
        acc[1][3] = fmaf(wv.y, xv.w, acc[1][3]);
        acc[2][0] = fmaf(wv.z, xv.x, acc[2][0]);
        acc[2][1] = fmaf(wv.z, xv.y, acc[2][1]);
        acc[2][2] = fmaf(wv.z, xv.z, acc[2][2]);
        acc[2][3] = fmaf(wv.z, xv.w, acc[2][3]);
        acc[3][0] = fmaf(wv.w, xv.x, acc[3][0]);
        acc[3][1] = fmaf(wv.w, xv.y, acc[3][1]);
        acc[3][2] = fmaf(wv.w, xv.z, acc[3][2]);
        acc[3][3] = fmaf(wv.w, xv.w, acc[3][3]);
    }

    const int co0 = m0 + ty * 4;
    float lsum = 0.f, lsq = 0.f;
#pragma unroll
    for (int mm = 0; mm < 4; mm++) {
        float bv = bias[co0 + mm];
#pragma unroll
        for (int j = 0; j < 4; j++) {
            float v = acc[mm][j] + bv;
            acc[mm][j] = v;
            lsum += v;
            lsq = fmaf(v, v, lsq);
        }
        *(float4*)&g_y[(long)(b * 128 + co0 + mm) * 4096 + n0 + tx * 4] =
            make_float4(acc[mm][0], acc[mm][1], acc[mm][2], acc[mm][3]);
    }

#pragma unroll
    for (int off = 16; off > 0; off >>= 1) {
        lsum += __shfl_xor_sync(0xffffffffu, lsum, off);
        lsq  += __shfl_xor_sync(0xffffffffu, lsq, off);
    }
    const int wid = tid >> 5, lane = tid & 31;
    if (lane == 0) { wred[wid][0] = lsum; wred[wid][1] = lsq; }
    __syncthreads();
    if (tid == 0) {
        float s0 = 0.f, q0 = 0.f, s1 = 0.f, q1 = 0.f;
#pragma unroll
        for (int ww = 0; ww < 4; ww++) { s0 += wred[ww][0]; q0 += wred[ww][1]; }
#pragma unroll
        for (int ww = 4; ww < 8; ww++) { s1 += wred[ww][0]; q1 += wred[ww][1]; }
        g_part[((b * 2 + blockIdx.y) * 64 + blockIdx.x) * 2 + 0] = make_float2(s0, q0);
        g_part[((b * 2 + blockIdx.y) * 64 + blockIdx.x) * 2 + 1] = make_float2(s1, q1);
    }
}

// ===========================================================================
// Kernel 3b: reduce GN partials. grid (4,4), 64 threads.
// ===========================================================================
__global__ void stats_kernel() {
    const int gg = blockIdx.x, b = blockIdx.y;
    const int by = gg >> 1, gl = gg & 1;
    const int t = threadIdx.x;
    float2 pv = g_part[((b * 2 + by) * 64 + t) * 2 + gl];
    float s = pv.x, ss = pv.y;
#pragma unroll
    for (int off = 16; off > 0; off >>= 1) {
        s  += __shfl_xor_sync(0xffffffffu, s, off);
        ss += __shfl_xor_sync(0xffffffffu, ss, off);
    }
    __shared__ float2 w2[2];
    if ((t & 31) == 0) w2[t >> 5] = make_float2(s, ss);
    __syncthreads();
    if (t == 0) {
        s = w2[0].x + w2[1].x;
        ss = w2[0].y + w2[1].y;
        const float invn = 1.f / 131072.f;
        float mean = s * invn;
        float var = ss * invn - mean * mean;
        g_stats[b * 4 + gg] = make_float2(mean, rsqrtf(var + GN_EPS));
    }
}

// ===========================================================================
// Kernel 4: GroupNorm affine + residual.
// ===========================================================================
__global__ __launch_bounds__(256) void norm_kernel(const float* __restrict__ x,
                                                   const float* __restrict__ gamma,
                                                   const float* __restrict__ beta,
                                                   float* __restrict__ out) {
    const int i4 = blockIdx.x * 256 + threadIdx.x;
    const int e = i4 * 4;
    const int c = (e >> 12) & 127;
    const int b = e >> 19;
    float2 st = g_stats[b * 4 + (c >> 5)];
    float ga = gamma[c] * st.y;
    float be = beta[c] - st.x * ga;
    float4 yv = *(const float4*)&g_y[e];
    float4 xv = *(const float4*)&x[e];
    float4 r;
    r.x = fmaf(yv.x, ga, be) + xv.x;
    r.y = fmaf(yv.y, ga, be) + xv.y;
    r.z = fmaf(yv.z, ga, be) + xv.z;
    r.w = fmaf(yv.w, ga, be) + xv.w;
    *(float4*)&out[e] = r;
}

// ===========================================================================
extern "C" void kernel_launch(void* const* d_in, const int* in_sizes, int n_in,
                              void* d_out, int out_size) {
    const float* x      = (const float*)d_in[0];
    const float* w_qkv  = (const float*)d_in[1];
    const float* w_out  = (const float*)d_in[2];
    const float* b_out  = (const float*)d_in[3];
    const float* gammap = (const float*)d_in[4];
    const float* betap  = (const float*)d_in[5];
    float* out = (float*)d_out;

    qkv_kernel<<<dim3(64, 6, 4), 256>>>(x, w_qkv);
    attn_kernel<<<dim3(64, 4, 4), 128>>>();
    proj_kernel<<<dim3(64, 2, 4), 256>>>(w_out, b_out);
    stats_kernel<<<dim3(4, 4), 64>>>();
    norm_kernel<<<2048, 256>>>(x, gammap, betap, out);
}

// round 4
// speedup vs baseline: 8.1406x; 1.7402x over previous
#include <cuda_runtime.h>
#include <cuda_fp16.h>

typedef unsigned int u32;

#define GN_EPS 1e-5f
// (1/sqrt(32)) * log2(e): softmax runs in base-2 domain
#define QSCALE 0.25501817097393111f

// ---------------- scratch (static device allocations, allowed) -------------
__device__ __align__(16) __half g_xh[4 * 128 * 4096];    // x in fp16 [b][c][n]
__device__ __align__(16) __half g_qh[4 * 4 * 4096 * 32]; // [b][h][n][d]
__device__ __align__(16) __half g_kh[4 * 4 * 4096 * 32];
__device__ __align__(16) __half g_vh[4 * 4 * 4096 * 32];
__device__ __align__(16) __half g_aoh[4 * 128 * 4096];   // attn out fp16 [b][c][n]
__device__ __align__(16) float g_y[4 * 128 * 4096];      // proj out fp32 [b][c][n]
__device__ float2 g_part[4 * 2 * 64 * 2];
__device__ float2 g_stats[16];

// ---------------- PTX helpers ----------------------------------------------
__device__ __forceinline__ float ex2(float x) {
    float r; asm("ex2.approx.ftz.f32 %0, %1;" : "=f"(r) : "f"(x)); return r;
}
__device__ __forceinline__ u32 ex2h2(u32 x) {
    u32 r; asm("ex2.approx.f16x2 %0, %1;" : "=r"(r) : "r"(x)); return r;
}
__device__ __forceinline__ void ldsm_x4(u32* r, u32 addr) {
    asm volatile("ldmatrix.sync.aligned.m8n8.x4.shared.b16 {%0,%1,%2,%3}, [%4];"
                 : "=r"(r[0]), "=r"(r[1]), "=r"(r[2]), "=r"(r[3]) : "r"(addr));
}
__device__ __forceinline__ void ldsm_x4_t(u32* r, u32 addr) {
    asm volatile("ldmatrix.sync.aligned.m8n8.x4.trans.shared.b16 {%0,%1,%2,%3}, [%4];"
                 : "=r"(r[0]), "=r"(r[1]), "=r"(r[2]), "=r"(r[3]) : "r"(addr));
}
__device__ __forceinline__ void mma16816(float* c, const u32* a, const u32* b) {
    asm volatile("mma.sync.aligned.m16n8k16.row.col.f32.f16.f16.f32 "
                 "{%0,%1,%2,%3}, {%4,%5,%6,%7}, {%8,%9}, {%0,%1,%2,%3};"
                 : "+f"(c[0]), "+f"(c[1]), "+f"(c[2]), "+f"(c[3])
                 : "r"(a[0]), "r"(a[1]), "r"(a[2]), "r"(a[3]), "r"(b[0]), "r"(b[1]));
}
__device__ __forceinline__ u32 packh2(float a, float b) {
    __half2 h = __floats2half2_rn(a, b);
    return *(u32*)&h;
}
__device__ __forceinline__ __half2 u2h(u32 x) { __half2 h; *(u32*)&h = x; return h; }
__device__ __forceinline__ void cp16(u32 smem, const void* gmem) {
    asm volatile("cp.async.cg.shared.global [%0], [%1], 16;" :: "r"(smem), "l"(gmem));
}

// ===========================================================================
// Kernel 0: convert x fp32 -> fp16
// ===========================================================================
__global__ __launch_bounds__(256) void cvt_kernel(const float* __restrict__ x) {
    const int i = blockIdx.x * 256 + threadIdx.x;  // 524288 float4s
    float4 v = *(const float4*)&x[i * 4];
    *(__half2*)&g_xh[i * 4 + 0] = __floats2half2_rn(v.x, v.y);
    *(__half2*)&g_xh[i * 4 + 2] = __floats2half2_rn(v.z, v.w);
}

// ===========================================================================
// Kernel 1: QKV projection on tensor cores.
// out[m,n] = sum_k W[m,k] * x[k,n].  Tile 64(m) x 64(n), k=128.
// grid (64, 6, 4), 128 threads (4 warps, 16 m-rows each).
// ===========================================================================
__global__ __launch_bounds__(128) void qkv_kernel(const float* __restrict__ w) {
    __shared__ __align__(16) char smemBuf[17408 + 18432];
    __half* Ws = (__half*)smemBuf;                 // [64][136]
    __half* Xs = (__half*)(smemBuf + 17408);       // [128][72]
    __half* Osh = (__half*)smemBuf;                // overlay after mainloop [64n][72]

    const int b = blockIdx.z;
    const int n0 = blockIdx.x * 64;
    const int m0 = blockIdx.y * 64;
    const int tid = threadIdx.x;
    const int wrp = tid >> 5, lane = tid & 31;

    // stage W (fp32 -> fp16), 64x128
    for (int idx = tid; idx < 64 * 32; idx += 128) {
        int row = idx >> 5, c4 = idx & 31;
        float4 wv = *(const float4*)&w[(m0 + row) * 128 + c4 * 4];
        *(__half2*)&Ws[row * 136 + c4 * 4 + 0] = __floats2half2_rn(wv.x, wv.y);
        *(__half2*)&Ws[row * 136 + c4 * 4 + 2] = __floats2half2_rn(wv.z, wv.w);
    }
    // stage X tile [k=128][n=64] fp16
    for (int idx = tid; idx < 128 * 8; idx += 128) {
        int row = idx >> 3, seg = idx & 7;
        *(uint4*)&Xs[row * 72 + seg * 8] =
            *(const uint4*)&g_xh[(b * 128 + row) * 4096 + n0 + seg * 8];
    }
    __syncthreads();

    float acc[8][4];
#pragma unroll
    for (int i = 0; i < 8; i++)
#pragma unroll
        for (int j = 0; j < 4; j++) acc[i][j] = 0.f;

    const u32 wsAddr = (u32)__cvta_generic_to_shared(
        &Ws[(wrp * 16 + (lane & 15)) * 136 + (lane >> 4) * 8]);
    const int vm = lane >> 3;
    const u32 xsAddr = (u32)__cvta_generic_to_shared(
        &Xs[((vm & 1) * 8 + (lane & 7)) * 72 + (vm >> 1) * 8]);

#pragma unroll
    for (int kk = 0; kk < 8; kk++) {
        u32 wa[4];
        ldsm_x4(wa, wsAddr + kk * 32);
#pragma unroll
        for (int np = 0; np < 4; np++) {
            u32 xb[4];
            ldsm_x4_t(xb, xsAddr + kk * 16 * 144 + np * 32);
            mma16816(acc[2 * np + 0], wa, xb + 0);
            mma16816(acc[2 * np + 1], wa, xb + 2);
        }
    }
    __syncthreads();   // done with Ws/Xs, reuse as Osh

    const float sc = (m0 < 128) ? QSCALE : 1.0f;
    const int g = lane >> 2, t4 = lane & 3;
#pragma unroll
    for (int nt = 0; nt < 8; nt++) {
        int col = nt * 8 + 2 * t4;
        int r0 = wrp * 16 + g;
        Osh[(col + 0) * 72 + r0 + 0] = __float2half(acc[nt][0] * sc);
        Osh[(col + 1) * 72 + r0 + 0] = __float2half(acc[nt][1] * sc);
        Osh[(col + 0) * 72 + r0 + 8] = __float2half(acc[nt][2] * sc);
        Osh[(col + 1) * 72 + r0 + 8] = __float2half(acc[nt][3] * sc);
    }
    __syncthreads();

    const int which = m0 >> 7;
    __half* dstbase = (which == 0) ? g_qh : ((which == 1) ? g_kh : g_vh);
    const int h0 = (m0 >> 5) & 3;
    const int n = tid >> 1, hi = tid & 1;
    __half* dst = &dstbase[((long)(b * 4 + h0 + hi) * 4096 + n0 + n) * 32];
    const __half* src = &Osh[n * 72 + hi * 32];
    *(uint4*)&dst[0]  = *(const uint4*)&src[0];
    *(uint4*)&dst[8]  = *(const uint4*)&src[8];
    *(uint4*)&dst[16] = *(const uint4*)&src[16];
    *(uint4*)&dst[24] = *(const uint4*)&src[24];
}

// ===========================================================================
// Kernel 2: fp16 tensor-core flash attention, cp.async double-buffered KV,
// f16x2 exp2.  grid (64, 4, 4), 128 threads.
// ===========================================================================
__global__ __launch_bounds__(128) void attn_kernel() {
    __shared__ __align__(16) __half Qs[64 * 40];
    __shared__ __align__(16) __half Ks[2][64 * 40];
    __shared__ __align__(16) __half Vs[2][64 * 40];
    __shared__ __align__(16) float Os[64 * 33];

    const int b = blockIdx.z, hh = blockIdx.y;
    const int q0 = blockIdx.x * 64;
    const int tid = threadIdx.x;
    const int wrp = tid >> 5, lane = tid & 31;
    const long bh = (long)(b * 4 + hh) * 4096;

    // stage Q tile
    {
        const uint4* qg = (const uint4*)&g_qh[(bh + q0) * 32];
        for (int i = tid; i < 256; i += 128) {
            int row = i >> 2, ch = i & 3;
            *(uint4*)&Qs[row * 40 + ch * 8] = qg[i];
        }
    }

    const uint4* kg = (const uint4*)&g_kh[bh * 32];
    const uint4* vg = (const uint4*)&g_vh[bh * 32];
    const u32 ksmem = (u32)__cvta_generic_to_shared(&Ks[0][0]);
    const u32 vsmem = (u32)__cvta_generic_to_shared(&Vs[0][0]);
    // per-thread cp.async slots: i = tid (rows 0-31), i+128 (rows 32-63)
    const u32 off0 = (tid >> 2) * 80 + (tid & 3) * 16;
    const u32 off1 = off0 + 32 * 80;

    // prologue: issue tile 0 into buf 0
    cp16(ksmem + off0, kg + tid);
    cp16(ksmem + off1, kg + tid + 128);
    cp16(vsmem + off0, vg + tid);
    cp16(vsmem + off1, vg + tid + 128);
    asm volatile("cp.async.commit_group;");

    __syncthreads();
    // Q A-fragments (held all kernel)
    u32 qa[8];
    {
        int r = lane & 15, cc = lane >> 4;
        u32 a = (u32)__cvta_generic_to_shared(&Qs[(wrp * 16 + r) * 40 + cc * 8]);
        ldsm_x4(qa + 0, a);
        ldsm_x4(qa + 4, a + 32);
    }

    float o[4][4];
#pragma unroll
    for (int i = 0; i < 4; i++)
#pragma unroll
        for (int j = 0; j < 4; j++) o[i][j] = 0.f;
    float m0 = -1e30f, m1 = -1e30f, l0 = 0.f, l1 = 0.f;

    const u32 kaddr = (u32)__cvta_generic_to_shared(
        &Ks[0][(lane & 7) * 40 + (lane >> 3) * 8]);
    const int vm = lane >> 3;
    const u32 vaddr = (u32)__cvta_generic_to_shared(
        &Vs[0][((vm & 1) * 8 + (lane & 7)) * 40 + (vm >> 1) * 8]);

    for (int t0 = 0; t0 < 4096; t0 += 64) {
        const int buf = (t0 >> 6) & 1;
        const u32 bo = buf * 5120;
        // prefetch next tile into other buffer
        if (t0 + 64 < 4096) {
            const uint4* ks = kg + (t0 + 64) * 4;
            const uint4* vs = vg + (t0 + 64) * 4;
            const u32 nb = (buf ^ 1) * 5120;
            cp16(ksmem + nb + off0, ks + tid);
            cp16(ksmem + nb + off1, ks + tid + 128);
            cp16(vsmem + nb + off0, vs + tid);
            cp16(vsmem + nb + off1, vs + tid + 128);
        }
        asm volatile("cp.async.commit_group;");
        asm volatile("cp.async.wait_group 1;");
        __syncthreads();

        // ---- S = Q K^T
        float s[8][4];
#pragma unroll
        for (int nt = 0; nt < 8; nt++) {
            s[nt][0] = s[nt][1] = s[nt][2] = s[nt][3] = 0.f;
            u32 kb[4];
            ldsm_x4(kb, kaddr + bo + nt * 640);
            mma16816(s[nt], qa + 0, kb + 0);
            mma16816(s[nt], qa + 4, kb + 2);
        }

        // ---- online softmax (base-2, f16x2 exp)
        float mx0 = -1e30f, mx1 = -1e30f;
#pragma unroll
        for (int nt = 0; nt < 8; nt++) {
            mx0 = fmaxf(mx0, fmaxf(s[nt][0], s[nt][1]));
            mx1 = fmaxf(mx1, fmaxf(s[nt][2], s[nt][3]));
        }
        mx0 = fmaxf(mx0, __shfl_xor_sync(0xffffffffu, mx0, 1));
        mx0 = fmaxf(mx0, __shfl_xor_sync(0xffffffffu, mx0, 2));
        mx1 = fmaxf(mx1, __shfl_xor_sync(0xffffffffu, mx1, 1));
        mx1 = fmaxf(mx1, __shfl_xor_sync(0xffffffffu, mx1, 2));
        float nm0 = fmaxf(m0, mx0), nm1 = fmaxf(m1, mx1);
        float corr0 = ex2(m0 - nm0), corr1 = ex2(m1 - nm1);
        m0 = nm0; m1 = nm1;

        u32 pa[8][2];
#pragma unroll
        for (int nt = 0; nt < 8; nt++) {
            pa[nt][0] = ex2h2(packh2(s[nt][0] - m0, s[nt][1] - m0));
            pa[nt][1] = ex2h2(packh2(s[nt][2] - m1, s[nt][3] - m1));
        }
        // l-sums via shallow half2 tree then fp32
        __half2 t00 = __hadd2(__hadd2(u2h(pa[0][0]), u2h(pa[1][0])),
                              __hadd2(u2h(pa[2][0]), u2h(pa[3][0])));
        __half2 t01 = __hadd2(__hadd2(u2h(pa[4][0]), u2h(pa[5][0])),
                              __hadd2(u2h(pa[6][0]), u2h(pa[7][0])));
        __half2 t10 = __hadd2(__hadd2(u2h(pa[0][1]), u2h(pa[1][1])),
                              __hadd2(u2h(pa[2][1]), u2h(pa[3][1])));
        __half2 t11 = __hadd2(__hadd2(u2h(pa[4][1]), u2h(pa[5][1])),
                              __hadd2(u2h(pa[6][1]), u2h(pa[7][1])));
        float2 f0 = __half22float2(__hadd2(t00, t01));
        float2 f1 = __half22float2(__hadd2(t10, t11));
        l0 = l0 * corr0 + f0.x + f0.y;
        l1 = l1 * corr1 + f1.x + f1.y;
#pragma unroll
        for (int nd = 0; nd < 4; nd++) {
            o[nd][0] *= corr0; o[nd][1] *= corr0;
            o[nd][2] *= corr1; o[nd][3] *= corr1;
        }

        // ---- O += P V
#pragma unroll
        for (int kv = 0; kv < 4; kv++) {
            u32 A[4] = {pa[2 * kv][0], pa[2 * kv][1],
                        pa[2 * kv + 1][0], pa[2 * kv + 1][1]};
#pragma unroll
            for (int dh = 0; dh < 2; dh++) {
                u32 vb[4];
                ldsm_x4_t(vb, vaddr + bo + kv * 1280 + dh * 32);
                mma16816(o[2 * dh + 0], A, vb + 0);
                mma16816(o[2 * dh + 1], A, vb + 2);
            }
        }
        __syncthreads();
    }

    // ---- epilogue
    l0 += __shfl_xor_sync(0xffffffffu, l0, 1);
    l0 += __shfl_xor_sync(0xffffffffu, l0, 2);
    l1 += __shfl_xor_sync(0xffffffffu, l1, 1);
    l1 += __shfl_xor_sync(0xffffffffu, l1, 2);
    const float inv0 = 1.f / l0, inv1 = 1.f / l1;
    const int grp = lane >> 2, t4 = lane & 3;
#pragma unroll
    for (int nd = 0; nd < 4; nd++) {
        Os[(wrp * 16 + grp) * 33 + nd * 8 + 2 * t4 + 0] = o[nd][0] * inv0;
        Os[(wrp * 16 + grp) * 33 + nd * 8 + 2 * t4 + 1] = o[nd][1] * inv0;
        Os[(wrp * 16 + grp + 8) * 33 + nd * 8 + 2 * t4 + 0] = o[nd][2] * inv1;
        Os[(wrp * 16 + grp + 8) * 33 + nd * 8 + 2 * t4 + 1] = o[nd][3] * inv1;
    }
    __syncthreads();

    __half* ob = &g_aoh[(long)(b * 128 + hh * 32) * 4096 + q0];
    const int dd = tid >> 2, seg = tid & 3;
    union { __half hx[16]; uint4 ux[2]; } tmp;
#pragma unroll
    for (int i = 0; i < 16; i++)
        tmp.hx[i] = __float2half(Os[(seg * 16 + i) * 33 + dd]);
    uint4* dsth = (uint4*)&ob[dd * 4096 + seg * 16];
    dsth[0] = tmp.ux[0];
    dsth[1] = tmp.ux[1];
}

// ===========================================================================
// Kernel 3: output projection on tensor cores + bias + GN partials.
// grid (64, 2, 4), 128 threads.
// ===========================================================================
__global__ __launch_bounds__(128) void proj_kernel(const float* __restrict__ w,
                                                   const float* __restrict__ bias) {
    __shared__ __align__(16) char smemBuf[17408 + 18432];
    __half* Ws = (__half*)smemBuf;              // [64][136]
    __half* Xs = (__half*)(smemBuf + 17408);    // [128][72]
    float* Osf = (float*)smemBuf;               // overlay [64m][68]
    __shared__ float wred[4][2];

    const int b = blockIdx.z;
    const int n0 = blockIdx.x * 64;
    const int m0 = blockIdx.y * 64;
    const int tid = threadIdx.x;
    const int wrp = tid >> 5, lane = tid & 31;

    for (int idx = tid; idx < 64 * 32; idx += 128) {
        int row = idx >> 5, c4 = idx & 31;
        float4 wv = *(const float4*)&w[(m0 + row) * 128 + c4 * 4];
        *(__half2*)&Ws[row * 136 + c4 * 4 + 0] = __floats2half2_rn(wv.x, wv.y);
        *(__half2*)&Ws[row * 136 + c4 * 4 + 2] = __floats2half2_rn(wv.z, wv.w);
    }
    for (int idx = tid; idx < 128 * 8; idx += 128) {
        int row = idx >> 3, seg = idx & 7;
        *(uint4*)&Xs[row * 72 + seg * 8] =
            *(const uint4*)&g_aoh[(long)(b * 128 + row) * 4096 + n0 + seg * 8];
    }
    __syncthreads();

    float acc[8][4];
#pragma unroll
    for (int i = 0; i < 8; i++)
#pragma unroll
        for (int j = 0; j < 4; j++) acc[i][j] = 0.f;

    const u32 wsAddr = (u32)__cvta_generic_to_shared(
        &Ws[(wrp * 16 + (lane & 15)) * 136 + (lane >> 4) * 8]);
    const int vm = lane >> 3;
    const u32 xsAddr = (u32)__cvta_generic_to_shared(
        &Xs[((vm & 1) * 8 + (lane & 7)) * 72 + (vm >> 1) * 8]);

#pragma unroll
    for (int kk = 0; kk < 8; kk++) {
        u32 wa[4];
        ldsm_x4(wa, wsAddr + kk * 32);
#pragma unroll
        for (int np = 0; np < 4; np++) {
            u32 xb[4];
            ldsm_x4_t(xb, xsAddr + kk * 16 * 144 + np * 32);
            mma16816(acc[2 * np + 0], wa, xb + 0);
            mma16816(acc[2 * np + 1], wa, xb + 2);
        }
    }
    __syncthreads();   // reuse smem as Osf

    const int g = lane >> 2, t4 = lane & 3;
    const int r0 = wrp * 16 + g;
    const float b0 = bias[m0 + r0], b1 = bias[m0 + r0 + 8];
    float lsum = 0.f, lsq = 0.f;
#pragma unroll
    for (int nt = 0; nt < 8; nt++) {
        int col = nt * 8 + 2 * t4;
        float v0 = acc[nt][0] + b0, v1 = acc[nt][1] + b0;
        float v2 = acc[nt][2] + b1, v3 = acc[nt][3] + b1;
        Osf[(r0 + 0) * 68 + col + 0] = v0;
        Osf[(r0 + 0) * 68 + col + 1] = v1;
        Osf[(r0 + 8) * 68 + col + 0] = v2;
        Osf[(r0 + 8) * 68 + col + 1] = v3;
        lsum += (v0 + v1) + (v2 + v3);
        lsq = fmaf(v0, v0, lsq); lsq = fmaf(v1, v1, lsq);
        lsq = fmaf(v2, v2, lsq); lsq = fmaf(v3, v3, lsq);
    }
#pragma unroll
    for (int off = 16; off > 0; off >>= 1) {
        lsum += __shfl_xor_sync(0xffffffffu, lsum, off);
        lsq  += __shfl_xor_sync(0xffffffffu, lsq, off);
    }
    if (lane == 0) { wred[wrp][0] = lsum; wred[wrp][1] = lsq; }
    __syncthreads();
    if (tid == 0) {
        float s0 = wred[0][0] + wred[1][0], q0 = wred[0][1] + wred[1][1];
        float s1 = wred[2][0] + wred[3][0], q1 = wred[2][1] + wred[3][1];
        g_part[((b * 2 + blockIdx.y) * 64 + blockIdx.x) * 2 + 0] = make_float2(s0, q0);
        g_part[((b * 2 + blockIdx.y) * 64 + blockIdx.x) * 2 + 1] = make_float2(s1, q1);
    }

    // coalesced write of y tile
    const int mrow = tid >> 1, seg = tid & 1;
    float* dst = &g_y[(long)(b * 128 + m0 + mrow) * 4096 + n0 + seg * 32];
    const float* src = &Osf[mrow * 68 + seg * 32];
#pragma unroll
    for (int j = 0; j < 8; j++)
        *(float4*)&dst[j * 4] = *(const float4*)&src[j * 4];
}

// ===========================================================================
// Kernel 3b: reduce GN partials. grid (4,4), 64 threads.
// ===========================================================================
__global__ void stats_kernel() {
    const int gg = blockIdx.x, b = blockIdx.y;
    const int by = gg >> 1, gl = gg & 1;
    const int t = threadIdx.x;
    float2 pv = g_part[((b * 2 + by) * 64 + t) * 2 + gl];
    float s = pv.x, ss = pv.y;
#pragma unroll
    for (int off = 16; off > 0; off >>= 1) {
        s  += __shfl_xor_sync(0xffffffffu, s, off);
        ss += __shfl_xor_sync(0xffffffffu, ss, off);
    }
    __shared__ float2 w2[2];
    if ((t & 31) == 0) w2[t >> 5] = make_float2(s, ss);
    __syncthreads();
    if (t == 0) {
        s = w2[0].x + w2[1].x;
        ss = w2[0].y + w2[1].y;
        const float invn = 1.f / 131072.f;
        float mean = s * invn;
        float var = ss * invn - mean * mean;
        g_stats[b * 4 + gg] = make_float2(mean, rsqrtf(var + GN_EPS));
    }
}

// ===========================================================================
// Kernel 4: GroupNorm affine + residual.
// ===========================================================================
__global__ __launch_bounds__(256) void norm_kernel(const float* __restrict__ x,
                                                   const float* __restrict__ gamma,
                                                   const float* __restrict__ beta,
                                                   float* __restrict__ out) {
    const int i4 = blockIdx.x * 256 + threadIdx.x;
    const int e = i4 * 4;
    const int c = (e >> 12) & 127;
    const int b = e >> 19;
    float2 st = g_stats[b * 4 + (c >> 5)];
    float ga = gamma[c] * st.y;
    float be = beta[c] - st.x * ga;
    float4 yv = *(const float4*)&g_y[e];
    float4 xv = *(const float4*)&x[e];
    float4 r;
    r.x = fmaf(yv.x, ga, be) + xv.x;
    r.y = fmaf(yv.y, ga, be) + xv.y;
    r.z = fmaf(yv.z, ga, be) + xv.z;
    r.w = fmaf(yv.w, ga, be) + xv.w;
    *(float4*)&out[e] = r;
}

// ===========================================================================
extern "C" void kernel_launch(void* const* d_in, const int* in_sizes, int n_in,
                              void* d_out, int out_size) {
    const float* x      = (const float*)d_in[0];
    const float* w_qkv  = (const float*)d_in[1];
    const float* w_out  = (const float*)d_in[2];
    const float* b_out  = (const float*)d_in[3];
    const float* gammap = (const float*)d_in[4];
    const float* betap  = (const float*)d_in[5];
    float* out = (float*)d_out;

    cvt_kernel<<<2048, 256>>>(x);
    qkv_kernel<<<dim3(64, 6, 4), 128>>>(w_qkv);
    attn_kernel<<<dim3(64, 4, 4), 128>>>();
    proj_kernel<<<dim3(64, 2, 4), 128>>>(w_out, b_out);
    stats_kernel<<<dim3(4, 4), 64>>>();
    norm_kernel<<<2048, 256>>>(x, gammap, betap, out);
}

// round 5
// speedup vs baseline: 8.1660x; 1.0031x over previous
#include <cuda_runtime.h>
#include <cuda_fp16.h>

typedef unsigned int u32;

#define GN_EPS 1e-5f
// (1/sqrt(32)) * log2(e): softmax runs in base-2 domain
#define QSCALE 0.25501817097393111f

// ---------------- scratch (static device allocations, allowed) -------------
__device__ __align__(16) __half g_xh[4 * 128 * 4096];    // x in fp16 [b][c][n]
__device__ __align__(16) __half g_qh[4 * 4 * 4096 * 32]; // [b][h][n][d]
__device__ __align__(16) __half g_kh[4 * 4 * 4096 * 32];
__device__ __align__(16) __half g_vh[4 * 4 * 4096 * 32];
__device__ __align__(16) __half g_aoh[4 * 128 * 4096];   // attn out fp16 [b][c][n]
__device__ __align__(16) float g_y[4 * 128 * 4096];      // proj out fp32 [b][c][n]
__device__ float2 g_part[4 * 2 * 64 * 2];
__device__ float2 g_stats[16];

// ---------------- PTX helpers ----------------------------------------------
__device__ __forceinline__ float ex2(float x) {
    float r; asm("ex2.approx.ftz.f32 %0, %1;" : "=f"(r) : "f"(x)); return r;
}
__device__ __forceinline__ u32 ex2h2(u32 x) {
    u32 r; asm("ex2.approx.f16x2 %0, %1;" : "=r"(r) : "r"(x)); return r;
}
__device__ __forceinline__ void ldsm_x4(u32* r, u32 addr) {
    asm volatile("ldmatrix.sync.aligned.m8n8.x4.shared.b16 {%0,%1,%2,%3}, [%4];"
                 : "=r"(r[0]), "=r"(r[1]), "=r"(r[2]), "=r"(r[3]) : "r"(addr));
}
__device__ __forceinline__ void ldsm_x4_t(u32* r, u32 addr) {
    asm volatile("ldmatrix.sync.aligned.m8n8.x4.trans.shared.b16 {%0,%1,%2,%3}, [%4];"
                 : "=r"(r[0]), "=r"(r[1]), "=r"(r[2]), "=r"(r[3]) : "r"(addr));
}
__device__ __forceinline__ void mma16816(float* c, const u32* a, const u32* b) {
    asm volatile("mma.sync.aligned.m16n8k16.row.col.f32.f16.f16.f32 "
                 "{%0,%1,%2,%3}, {%4,%5,%6,%7}, {%8,%9}, {%0,%1,%2,%3};"
                 : "+f"(c[0]), "+f"(c[1]), "+f"(c[2]), "+f"(c[3])
                 : "r"(a[0]), "r"(a[1]), "r"(a[2]), "r"(a[3]), "r"(b[0]), "r"(b[1]));
}
__device__ __forceinline__ u32 packh2(float a, float b) {
    __half2 h = __floats2half2_rn(a, b);
    return *(u32*)&h;
}
__device__ __forceinline__ __half2 u2h(u32 x) { __half2 h; *(u32*)&h = x; return h; }
__device__ __forceinline__ void cp16(u32 smem, const void* gmem) {
    asm volatile("cp.async.cg.shared.global [%0], [%1], 16;" :: "r"(smem), "l"(gmem));
}

// ===========================================================================
// Kernel 0: convert x fp32 -> fp16
// ===========================================================================
__global__ __launch_bounds__(256) void cvt_kernel(const float* __restrict__ x) {
    const int i = blockIdx.x * 256 + threadIdx.x;  // 524288 float4s
    float4 v = *(const float4*)&x[i * 4];
    *(__half2*)&g_xh[i * 4 + 0] = __floats2half2_rn(v.x, v.y);
    *(__half2*)&g_xh[i * 4 + 2] = __floats2half2_rn(v.z, v.w);
}

// ===========================================================================
// Kernel 1: QKV projection on tensor cores.
// out[m,n] = sum_k W[m,k] * x[k,n].  Tile 64(m) x 64(n), k=128.
// grid (64, 6, 4), 128 threads (4 warps, 16 m-rows each).
// ===========================================================================
__global__ __launch_bounds__(128) void qkv_kernel(const float* __restrict__ w) {
    __shared__ __align__(16) char smemBuf[17408 + 18432];
    __half* Ws = (__half*)smemBuf;                 // [64][136]
    __half* Xs = (__half*)(smemBuf + 17408);       // [128][72]
    __half* Osh = (__half*)smemBuf;                // overlay after mainloop [64n][72]

    const int b = blockIdx.z;
    const int n0 = blockIdx.x * 64;
    const int m0 = blockIdx.y * 64;
    const int tid = threadIdx.x;
    const int wrp = tid >> 5, lane = tid & 31;

    // stage W (fp32 -> fp16), 64x128
    for (int idx = tid; idx < 64 * 32; idx += 128) {
        int row = idx >> 5, c4 = idx & 31;
        float4 wv = *(const float4*)&w[(m0 + row) * 128 + c4 * 4];
        *(__half2*)&Ws[row * 136 + c4 * 4 + 0] = __floats2half2_rn(wv.x, wv.y);
        *(__half2*)&Ws[row * 136 + c4 * 4 + 2] = __floats2half2_rn(wv.z, wv.w);
    }
    // stage X tile [k=128][n=64] fp16
    for (int idx = tid; idx < 128 * 8; idx += 128) {
        int row = idx >> 3, seg = idx & 7;
        *(uint4*)&Xs[row * 72 + seg * 8] =
            *(const uint4*)&g_xh[(b * 128 + row) * 4096 + n0 + seg * 8];
    }
    __syncthreads();

    float acc[8][4];
#pragma unroll
    for (int i = 0; i < 8; i++)
#pragma unroll
        for (int j = 0; j < 4; j++) acc[i][j] = 0.f;

    const u32 wsAddr = (u32)__cvta_generic_to_shared(
        &Ws[(wrp * 16 + (lane & 15)) * 136 + (lane >> 4) * 8]);
    const int vm = lane >> 3;
    const u32 xsAddr = (u32)__cvta_generic_to_shared(
        &Xs[((vm & 1) * 8 + (lane & 7)) * 72 + (vm >> 1) * 8]);

#pragma unroll
    for (int kk = 0; kk < 8; kk++) {
        u32 wa[4];
        ldsm_x4(wa, wsAddr + kk * 32);
#pragma unroll
        for (int np = 0; np < 4; np++) {
            u32 xb[4];
            ldsm_x4_t(xb, xsAddr + kk * 16 * 144 + np * 32);
            mma16816(acc[2 * np + 0], wa, xb + 0);
            mma16816(acc[2 * np + 1], wa, xb + 2);
        }
    }
    __syncthreads();   // done with Ws/Xs, reuse as Osh

    const float sc = (m0 < 128) ? QSCALE : 1.0f;
    const int g = lane >> 2, t4 = lane & 3;
#pragma unroll
    for (int nt = 0; nt < 8; nt++) {
        int col = nt * 8 + 2 * t4;
        int r0 = wrp * 16 + g;
        Osh[(col + 0) * 72 + r0 + 0] = __float2half(acc[nt][0] * sc);
        Osh[(col + 1) * 72 + r0 + 0] = __float2half(acc[nt][1] * sc);
        Osh[(col + 0) * 72 + r0 + 8] = __float2half(acc[nt][2] * sc);
        Osh[(col + 1) * 72 + r0 + 8] = __float2half(acc[nt][3] * sc);
    }
    __syncthreads();

    const int which = m0 >> 7;
    __half* dstbase = (which == 0) ? g_qh : ((which == 1) ? g_kh : g_vh);
    const int h0 = (m0 >> 5) & 3;
    const int n = tid >> 1, hi = tid & 1;
    __half* dst = &dstbase[((long)(b * 4 + h0 + hi) * 4096 + n0 + n) * 32];
    const __half* src = &Osh[n * 72 + hi * 32];
    *(uint4*)&dst[0]  = *(const uint4*)&src[0];
    *(uint4*)&dst[8]  = *(const uint4*)&src[8];
    *(uint4*)&dst[16] = *(const uint4*)&src[16];
    *(uint4*)&dst[24] = *(const uint4*)&src[24];
}

// ===========================================================================
// Kernel 2: fp16 tensor-core flash attention, cp.async double-buffered KV,
// f16x2 exp2.  grid (64, 4, 4), 128 threads.
// ===========================================================================
__global__ __launch_bounds__(128) void attn_kernel() {
    __shared__ __align__(16) __half Qs[64 * 40];
    __shared__ __align__(16) __half Ks[2][64 * 40];
    __shared__ __align__(16) __half Vs[2][64 * 40];
    __shared__ __align__(16) float Os[64 * 33];

    const int b = blockIdx.z, hh = blockIdx.y;
    const int q0 = blockIdx.x * 64;
    const int tid = threadIdx.x;
    const int wrp = tid >> 5, lane = tid & 31;
    const long bh = (long)(b * 4 + hh) * 4096;

    // stage Q tile
    {
        const uint4* qg = (const uint4*)&g_qh[(bh + q0) * 32];
        for (int i = tid; i < 256; i += 128) {
            int row = i >> 2, ch = i & 3;
            *(uint4*)&Qs[row * 40 + ch * 8] = qg[i];
        }
    }

    const uint4* kg = (const uint4*)&g_kh[bh * 32];
    const uint4* vg = (const uint4*)&g_vh[bh * 32];
    const u32 ksmem = (u32)__cvta_generic_to_shared(&Ks[0][0]);
    const u32 vsmem = (u32)__cvta_generic_to_shared(&Vs[0][0]);
    // per-thread cp.async slots: i = tid (rows 0-31), i+128 (rows 32-63)
    const u32 off0 = (tid >> 2) * 80 + (tid & 3) * 16;
    const u32 off1 = off0 + 32 * 80;

    // prologue: issue tile 0 into buf 0
    cp16(ksmem + off0, kg + tid);
    cp16(ksmem + off1, kg + tid + 128);
    cp16(vsmem + off0, vg + tid);
    cp16(vsmem + off1, vg + tid + 128);
    asm volatile("cp.async.commit_group;");

    __syncthreads();
    // Q A-fragments (held all kernel)
    u32 qa[8];
    {
        int r = lane & 15, cc = lane >> 4;
        u32 a = (u32)__cvta_generic_to_shared(&Qs[(wrp * 16 + r) * 40 + cc * 8]);
        ldsm_x4(qa + 0, a);
        ldsm_x4(qa + 4, a + 32);
    }

    float o[4][4];
#pragma unroll
    for (int i = 0; i < 4; i++)
#pragma unroll
        for (int j = 0; j < 4; j++) o[i][j] = 0.f;
    float m0 = -1e30f, m1 = -1e30f, l0 = 0.f, l1 = 0.f;

    const u32 kaddr = (u32)__cvta_generic_to_shared(
        &Ks[0][(lane & 7) * 40 + (lane >> 3) * 8]);
    const int vm = lane >> 3;
    const u32 vaddr = (u32)__cvta_generic_to_shared(
        &Vs[0][((vm & 1) * 8 + (lane & 7)) * 40 + (vm >> 1) * 8]);

    for (int t0 = 0; t0 < 4096; t0 += 64) {
        const int buf = (t0 >> 6) & 1;
        const u32 bo = buf * 5120;
        // prefetch next tile into other buffer
        if (t0 + 64 < 4096) {
            const uint4* ks = kg + (t0 + 64) * 4;
            const uint4* vs = vg + (t0 + 64) * 4;
            const u32 nb = (buf ^ 1) * 5120;
            cp16(ksmem + nb + off0, ks + tid);
            cp16(ksmem + nb + off1, ks + tid + 128);
            cp16(vsmem + nb + off0, vs + tid);
            cp16(vsmem + nb + off1, vs + tid + 128);
        }
        asm volatile("cp.async.commit_group;");
        asm volatile("cp.async.wait_group 1;");
        __syncthreads();

        // ---- S = Q K^T
        float s[8][4];
#pragma unroll
        for (int nt = 0; nt < 8; nt++) {
            s[nt][0] = s[nt][1] = s[nt][2] = s[nt][3] = 0.f;
            u32 kb[4];
            ldsm_x4(kb, kaddr + bo + nt * 640);
            mma16816(s[nt], qa + 0, kb + 0);
            mma16816(s[nt], qa + 4, kb + 2);
        }

        // ---- online softmax (base-2, f16x2 exp)
        float mx0 = -1e30f, mx1 = -1e30f;
#pragma unroll
        for (int nt = 0; nt < 8; nt++) {
            mx0 = fmaxf(mx0, fmaxf(s[nt][0], s[nt][1]));
            mx1 = fmaxf(mx1, fmaxf(s[nt][2], s[nt][3]));
        }
        mx0 = fmaxf(mx0, __shfl_xor_sync(0xffffffffu, mx0, 1));
        mx0 = fmaxf(mx0, __shfl_xor_sync(0xffffffffu, mx0, 2));
        mx1 = fmaxf(mx1, __shfl_xor_sync(0xffffffffu, mx1, 1));
        mx1 = fmaxf(mx1, __shfl_xor_sync(0xffffffffu, mx1, 2));
        float nm0 = fmaxf(m0, mx0), nm1 = fmaxf(m1, mx1);
        float corr0 = ex2(m0 - nm0), corr1 = ex2(m1 - nm1);
        m0 = nm0; m1 = nm1;

        u32 pa[8][2];
#pragma unroll
        for (int nt = 0; nt < 8; nt++) {
            pa[nt][0] = ex2h2(packh2(s[nt][0] - m0, s[nt][1] - m0));
            pa[nt][1] = ex2h2(packh2(s[nt][2] - m1, s[nt][3] - m1));
        }
        // l-sums via shallow half2 tree then fp32
        __half2 t00 = __hadd2(__hadd2(u2h(pa[0][0]), u2h(pa[1][0])),
                              __hadd2(u2h(pa[2][0]), u2h(pa[3][0])));
        __half2 t01 = __hadd2(__hadd2(u2h(pa[4][0]), u2h(pa[5][0])),
                              __hadd2(u2h(pa[6][0]), u2h(pa[7][0])));
        __half2 t10 = __hadd2(__hadd2(u2h(pa[0][1]), u2h(pa[1][1])),
                              __hadd2(u2h(pa[2][1]), u2h(pa[3][1])));
        __half2 t11 = __hadd2(__hadd2(u2h(pa[4][1]), u2h(pa[5][1])),
                              __hadd2(u2h(pa[6][1]), u2h(pa[7][1])));
        float2 f0 = __half22float2(__hadd2(t00, t01));
        float2 f1 = __half22float2(__hadd2(t10, t11));
        l0 = l0 * corr0 + f0.x + f0.y;
        l1 = l1 * corr1 + f1.x + f1.y;
#pragma unroll
        for (int nd = 0; nd < 4; nd++) {
            o[nd][0] *= corr0; o[nd][1] *= corr0;
            o[nd][2] *= corr1; o[nd][3] *= corr1;
        }

        // ---- O += P V
#pragma unroll
        for (int kv = 0; kv < 4; kv++) {
            u32 A[4] = {pa[2 * kv][0], pa[2 * kv][1],
                        pa[2 * kv + 1][0], pa[2 * kv + 1][1]};
#pragma unroll
            for (int dh = 0; dh < 2; dh++) {
                u32 vb[4];
                ldsm_x4_t(vb, vaddr + bo + kv * 1280 + dh * 32);
                mma16816(o[2 * dh + 0], A, vb + 0);
                mma16816(o[2 * dh + 1], A, vb + 2);
            }
        }
        __syncthreads();
    }

    // ---- epilogue
    l0 += __shfl_xor_sync(0xffffffffu, l0, 1);
    l0 += __shfl_xor_sync(0xffffffffu, l0, 2);
    l1 += __shfl_xor_sync(0xffffffffu, l1, 1);
    l1 += __shfl_xor_sync(0xffffffffu, l1, 2);
    const float inv0 = 1.f / l0, inv1 = 1.f / l1;
    const int grp = lane >> 2, t4 = lane & 3;
#pragma unroll
    for (int nd = 0; nd < 4; nd++) {
        Os[(wrp * 16 + grp) * 33 + nd * 8 + 2 * t4 + 0] = o[nd][0] * inv0;
        Os[(wrp * 16 + grp) * 33 + nd * 8 + 2 * t4 + 1] = o[nd][1] * inv0;
        Os[(wrp * 16 + grp + 8) * 33 + nd * 8 + 2 * t4 + 0] = o[nd][2] * inv1;
        Os[(wrp * 16 + grp + 8) * 33 + nd * 8 + 2 * t4 + 1] = o[nd][3] * inv1;
    }
    __syncthreads();

    __half* ob = &g_aoh[(long)(b * 128 + hh * 32) * 4096 + q0];
    const int dd = tid >> 2, seg = tid & 3;
    union { __half hx[16]; uint4 ux[2]; } tmp;
#pragma unroll
    for (int i = 0; i < 16; i++)
        tmp.hx[i] = __float2half(Os[(seg * 16 + i) * 33 + dd]);
    uint4* dsth = (uint4*)&ob[dd * 4096 + seg * 16];
    dsth[0] = tmp.ux[0];
    dsth[1] = tmp.ux[1];
}

// ===========================================================================
// Kernel 3: output projection on tensor cores + bias + GN partials.
// grid (64, 2, 4), 128 threads.
// ===========================================================================
__global__ __launch_bounds__(128) void proj_kernel(const float* __restrict__ w,
                                                   const float* __restrict__ bias) {
    __shared__ __align__(16) char smemBuf[17408 + 18432];
    __half* Ws = (__half*)smemBuf;              // [64][136]
    __half* Xs = (__half*)(smemBuf + 17408);    // [128][72]
    float* Osf = (float*)smemBuf;               // overlay [64m][68]
    __shared__ float wred[4][2];

    const int b = blockIdx.z;
    const int n0 = blockIdx.x * 64;
    const int m0 = blockIdx.y * 64;
    const int tid = threadIdx.x;
    const int wrp = tid >> 5, lane = tid & 31;

    for (int idx = tid; idx < 64 * 32; idx += 128) {
        int row = idx >> 5, c4 = idx & 31;
        float4 wv = *(const float4*)&w[(m0 + row) * 128 + c4 * 4];
        *(__half2*)&Ws[row * 136 + c4 * 4 + 0] = __floats2half2_rn(wv.x, wv.y);
        *(__half2*)&Ws[row * 136 + c4 * 4 + 2] = __floats2half2_rn(wv.z, wv.w);
    }
    for (int idx = tid; idx < 128 * 8; idx += 128) {
        int row = idx >> 3, seg = idx & 7;
        *(uint4*)&Xs[row * 72 + seg * 8] =
            *(const uint4*)&g_aoh[(long)(b * 128 + row) * 4096 + n0 + seg * 8];
    }
    __syncthreads();

    float acc[8][4];
#pragma unroll
    for (int i = 0; i < 8; i++)
#pragma unroll
        for (int j = 0; j < 4; j++) acc[i][j] = 0.f;

    const u32 wsAddr = (u32)__cvta_generic_to_shared(
        &Ws[(wrp * 16 + (lane & 15)) * 136 + (lane >> 4) * 8]);
    const int vm = lane >> 3;
    const u32 xsAddr = (u32)__cvta_generic_to_shared(
        &Xs[((vm & 1) * 8 + (lane & 7)) * 72 + (vm >> 1) * 8]);

#pragma unroll
    for (int kk = 0; kk < 8; kk++) {
        u32 wa[4];
        ldsm_x4(wa, wsAddr + kk * 32);
#pragma unroll
        for (int np = 0; np < 4; np++) {
            u32 xb[4];
            ldsm_x4_t(xb, xsAddr + kk * 16 * 144 + np * 32);
            mma16816(acc[2 * np + 0], wa, xb + 0);
            mma16816(acc[2 * np + 1], wa, xb + 2);
        }
    }
    __syncthreads();   // reuse smem as Osf

    const int g = lane >> 2, t4 = lane & 3;
    const int r0 = wrp * 16 + g;
    const float b0 = bias[m0 + r0], b1 = bias[m0 + r0 + 8];
    float lsum = 0.f, lsq = 0.f;
#pragma unroll
    for (int nt = 0; nt < 8; nt++) {
        int col = nt * 8 + 2 * t4;
        float v0 = acc[nt][0] + b0, v1 = acc[nt][1] + b0;
        float v2 = acc[nt][2] + b1, v3 = acc[nt][3] + b1;
        Osf[(r0 + 0) * 68 + col + 0] = v0;
        Osf[(r0 + 0) * 68 + col + 1] = v1;
        Osf[(r0 + 8) * 68 + col + 0] = v2;
        Osf[(r0 + 8) * 68 + col + 1] = v3;
        lsum += (v0 + v1) + (v2 + v3);
        lsq = fmaf(v0, v0, lsq); lsq = fmaf(v1, v1, lsq);
        lsq = fmaf(v2, v2, lsq); lsq = fmaf(v3, v3, lsq);
    }
#pragma unroll
    for (int off = 16; off > 0; off >>= 1) {
        lsum += __shfl_xor_sync(0xffffffffu, lsum, off);
        lsq  += __shfl_xor_sync(0xffffffffu, lsq, off);
    }
    if (lane == 0) { wred[wrp][0] = lsum; wred[wrp][1] = lsq; }
    __syncthreads();
    if (tid == 0) {
        float s0 = wred[0][0] + wred[1][0], q0 = wred[0][1] + wred[1][1];
        float s1 = wred[2][0] + wred[3][0], q1 = wred[2][1] + wred[3][1];
        g_part[((b * 2 + blockIdx.y) * 64 + blockIdx.x) * 2 + 0] = make_float2(s0, q0);
        g_part[((b * 2 + blockIdx.y) * 64 + blockIdx.x) * 2 + 1] = make_float2(s1, q1);
    }

    // coalesced write of y tile
    const int mrow = tid >> 1, seg = tid & 1;
    float* dst = &g_y[(long)(b * 128 + m0 + mrow) * 4096 + n0 + seg * 32];
    const float* src = &Osf[mrow * 68 + seg * 32];
#pragma unroll
    for (int j = 0; j < 8; j++)
        *(float4*)&dst[j * 4] = *(const float4*)&src[j * 4];
}

// ===========================================================================
// Kernel 3b: reduce GN partials. grid (4,4), 64 threads.
// ===========================================================================
__global__ void stats_kernel() {
    const int gg = blockIdx.x, b = blockIdx.y;
    const int by = gg >> 1, gl = gg & 1;
    const int t = threadIdx.x;
    float2 pv = g_part[((b * 2 + by) * 64 + t) * 2 + gl];
    float s = pv.x, ss = pv.y;
#pragma unroll
    for (int off = 16; off > 0; off >>= 1) {
        s  += __shfl_xor_sync(0xffffffffu, s, off);
        ss += __shfl_xor_sync(0xffffffffu, ss, off);
    }
    __shared__ float2 w2[2];
    if ((t & 31) == 0) w2[t >> 5] = make_float2(s, ss);
    __syncthreads();
    if (t == 0) {
        s = w2[0].x + w2[1].x;
        ss = w2[0].y + w2[1].y;
        const float invn = 1.f / 131072.f;
        float mean = s * invn;
        float var = ss * invn - mean * mean;
        g_stats[b * 4 + gg] = make_float2(mean, rsqrtf(var + GN_EPS));
    }
}

// ===========================================================================
// Kernel 4: GroupNorm affine + residual.
// ===========================================================================
__global__ __launch_bounds__(256) void norm_kernel(const float* __restrict__ x,
                                                   const float* __restrict__ gamma,
                                                   const float* __restrict__ beta,
                                                   float* __restrict__ out) {
    const int i4 = blockIdx.x * 256 + threadIdx.x;
    const int e = i4 * 4;
    const int c = (e >> 12) & 127;
    const int b = e >> 19;
    float2 st = g_stats[b * 4 + (c >> 5)];
    float ga = gamma[c] * st.y;
    float be = beta[c] - st.x * ga;
    float4 yv = *(const float4*)&g_y[e];
    float4 xv = *(const float4*)&x[e];
    float4 r;
    r.x = fmaf(yv.x, ga, be) + xv.x;
    r.y = fmaf(yv.y, ga, be) + xv.y;
    r.z = fmaf(yv.z, ga, be) + xv.z;
    r.w = fmaf(yv.w, ga, be) + xv.w;
    *(float4*)&out[e] = r;
}

// ===========================================================================
extern "C" void kernel_launch(void* const* d_in, const int* in_sizes, int n_in,
                              void* d_out, int out_size) {
    const float* x      = (const float*)d_in[0];
    const float* w_qkv  = (const float*)d_in[1];
    const float* w_out  = (const float*)d_in[2];
    const float* b_out  = (const float*)d_in[3];
    const float* gammap = (const float*)d_in[4];
    const float* betap  = (const float*)d_in[5];
    float* out = (float*)d_out;

    cvt_kernel<<<2048, 256>>>(x);
    qkv_kernel<<<dim3(64, 6, 4), 128>>>(w_qkv);
    attn_kernel<<<dim3(64, 4, 4), 128>>>();
    proj_kernel<<<dim3(64, 2, 4), 128>>>(w_out, b_out);
    stats_kernel<<<dim3(4, 4), 64>>>();
    norm_kernel<<<2048, 256>>>(x, gammap, betap, out);
}

// round 6
// speedup vs baseline: 8.1720x; 1.0007x over previous
#include <cuda_runtime.h>
#include <cuda_fp16.h>

typedef unsigned int u32;

#define GN_EPS 1e-5f
// (1/sqrt(32)) * log2(e): softmax runs in base-2 domain
#define QSCALE 0.25501817097393111f

// ---------------- scratch (static device allocations, allowed) -------------
__device__ __align__(16) __half g_xh[4 * 128 * 4096];    // x in fp16 [b][c][n]
__device__ __align__(16) __half g_qh[4 * 4 * 4096 * 32]; // [b][h][n][d]
__device__ __align__(16) __half g_kh[4 * 4 * 4096 * 32];
__device__ __align__(16) __half g_vh[4 * 4 * 4096 * 32];
__device__ __align__(16) __half g_aoh[4 * 128 * 4096];   // attn out fp16 [b][c][n]
__device__ __align__(16) float g_y[4 * 128 * 4096];      // proj out fp32 [b][c][n]
__device__ float2 g_part[4 * 2 * 64 * 2];
__device__ float2 g_stats[16];

// ---------------- PTX helpers ----------------------------------------------
__device__ __forceinline__ float ex2(float x) {
    float r; asm("ex2.approx.ftz.f32 %0, %1;" : "=f"(r) : "f"(x)); return r;
}
__device__ __forceinline__ u32 ex2h2(u32 x) {
    u32 r; asm("ex2.approx.f16x2 %0, %1;" : "=r"(r) : "r"(x)); return r;
}
__device__ __forceinline__ void ldsm_x4(u32* r, u32 addr) {
    asm volatile("ldmatrix.sync.aligned.m8n8.x4.shared.b16 {%0,%1,%2,%3}, [%4];"
                 : "=r"(r[0]), "=r"(r[1]), "=r"(r[2]), "=r"(r[3]) : "r"(addr));
}
__device__ __forceinline__ void ldsm_x4_t(u32* r, u32 addr) {
    asm volatile("ldmatrix.sync.aligned.m8n8.x4.trans.shared.b16 {%0,%1,%2,%3}, [%4];"
                 : "=r"(r[0]), "=r"(r[1]), "=r"(r[2]), "=r"(r[3]) : "r"(addr));
}
__device__ __forceinline__ void mma16816(float* c, const u32* a, const u32* b) {
    asm volatile("mma.sync.aligned.m16n8k16.row.col.f32.f16.f16.f32 "
                 "{%0,%1,%2,%3}, {%4,%5,%6,%7}, {%8,%9}, {%0,%1,%2,%3};"
                 : "+f"(c[0]), "+f"(c[1]), "+f"(c[2]), "+f"(c[3])
                 : "r"(a[0]), "r"(a[1]), "r"(a[2]), "r"(a[3]), "r"(b[0]), "r"(b[1]));
}
__device__ __forceinline__ u32 packh2(float a, float b) {
    __half2 h = __floats2half2_rn(a, b);
    return *(u32*)&h;
}
__device__ __forceinline__ __half2 u2h(u32 x) { __half2 h; *(u32*)&h = x; return h; }
__device__ __forceinline__ void cp16(u32 smem, const void* gmem) {
    asm volatile("cp.async.cg.shared.global [%0], [%1], 16;" :: "r"(smem), "l"(gmem));
}

// ===========================================================================
// Kernel 0: convert x fp32 -> fp16
// ===========================================================================
__global__ __launch_bounds__(256) void cvt_kernel(const float* __restrict__ x) {
    const int i = blockIdx.x * 256 + threadIdx.x;  // 524288 float4s
    float4 v = *(const float4*)&x[i * 4];
    *(__half2*)&g_xh[i * 4 + 0] = __floats2half2_rn(v.x, v.y);
    *(__half2*)&g_xh[i * 4 + 2] = __floats2half2_rn(v.z, v.w);
}

// ===========================================================================
// Kernel 1: QKV projection on tensor cores.
// out[m,n] = sum_k W[m,k] * x[k,n].  Tile 64(m) x 64(n), k=128.
// grid (64, 6, 4), 128 threads (4 warps, 16 m-rows each).
// ===========================================================================
__global__ __launch_bounds__(128) void qkv_kernel(const float* __restrict__ w) {
    __shared__ __align__(16) char smemBuf[17408 + 18432];
    __half* Ws = (__half*)smemBuf;                 // [64][136]
    __half* Xs = (__half*)(smemBuf + 17408);       // [128][72]
    __half* Osh = (__half*)smemBuf;                // overlay after mainloop [64n][72]

    const int b = blockIdx.z;
    const int n0 = blockIdx.x * 64;
    const int m0 = blockIdx.y * 64;
    const int tid = threadIdx.x;
    const int wrp = tid >> 5, lane = tid & 31;

    // stage W (fp32 -> fp16), 64x128
    for (int idx = tid; idx < 64 * 32; idx += 128) {
        int row = idx >> 5, c4 = idx & 31;
        float4 wv = *(const float4*)&w[(m0 + row) * 128 + c4 * 4];
        *(__half2*)&Ws[row * 136 + c4 * 4 + 0] = __floats2half2_rn(wv.x, wv.y);
        *(__half2*)&Ws[row * 136 + c4 * 4 + 2] = __floats2half2_rn(wv.z, wv.w);
    }
    // stage X tile [k=128][n=64] fp16
    for (int idx = tid; idx < 128 * 8; idx += 128) {
        int row = idx >> 3, seg = idx & 7;
        *(uint4*)&Xs[row * 72 + seg * 8] =
            *(const uint4*)&g_xh[(b * 128 + row) * 4096 + n0 + seg * 8];
    }
    __syncthreads();

    float acc[8][4];
#pragma unroll
    for (int i = 0; i < 8; i++)
#pragma unroll
        for (int j = 0; j < 4; j++) acc[i][j] = 0.f;

    const u32 wsAddr = (u32)__cvta_generic_to_shared(
        &Ws[(wrp * 16 + (lane & 15)) * 136 + (lane >> 4) * 8]);
    const int vm = lane >> 3;
    const u32 xsAddr = (u32)__cvta_generic_to_shared(
        &Xs[((vm & 1) * 8 + (lane & 7)) * 72 + (vm >> 1) * 8]);

#pragma unroll
    for (int kk = 0; kk < 8; kk++) {
        u32 wa[4];
        ldsm_x4(wa, wsAddr + kk * 32);
#pragma unroll
        for (int np = 0; np < 4; np++) {
            u32 xb[4];
            ldsm_x4_t(xb, xsAddr + kk * 16 * 144 + np * 32);
            mma16816(acc[2 * np + 0], wa, xb + 0);
            mma16816(acc[2 * np + 1], wa, xb + 2);
        }
    }
    __syncthreads();   // done with Ws/Xs, reuse as Osh

    const float sc = (m0 < 128) ? QSCALE : 1.0f;
    const int g = lane >> 2, t4 = lane & 3;
#pragma unroll
    for (int nt = 0; nt < 8; nt++) {
        int col = nt * 8 + 2 * t4;
        int r0 = wrp * 16 + g;
        Osh[(col + 0) * 72 + r0 + 0] = __float2half(acc[nt][0] * sc);
        Osh[(col + 1) * 72 + r0 + 0] = __float2half(acc[nt][1] * sc);
        Osh[(col + 0) * 72 + r0 + 8] = __float2half(acc[nt][2] * sc);
        Osh[(col + 1) * 72 + r0 + 8] = __float2half(acc[nt][3] * sc);
    }
    __syncthreads();

    const int which = m0 >> 7;
    __half* dstbase = (which == 0) ? g_qh : ((which == 1) ? g_kh : g_vh);
    const int h0 = (m0 >> 5) & 3;
    const int n = tid >> 1, hi = tid & 1;
    __half* dst = &dstbase[((long)(b * 4 + h0 + hi) * 4096 + n0 + n) * 32];
    const __half* src = &Osh[n * 72 + hi * 32];
    *(uint4*)&dst[0]  = *(const uint4*)&src[0];
    *(uint4*)&dst[8]  = *(const uint4*)&src[8];
    *(uint4*)&dst[16] = *(const uint4*)&src[16];
    *(uint4*)&dst[24] = *(const uint4*)&src[24];
}

// ===========================================================================
// Kernel 2: fp16 tensor-core flash attention, cp.async double-buffered KV,
// f16x2 exp2.  grid (64, 4, 4), 128 threads.
// ===========================================================================
__global__ __launch_bounds__(128) void attn_kernel() {
    __shared__ __align__(16) __half Qs[64 * 40];
    __shared__ __align__(16) __half Ks[2][64 * 40];
    __shared__ __align__(16) __half Vs[2][64 * 40];
    __shared__ __align__(16) float Os[64 * 33];

    const int b = blockIdx.z, hh = blockIdx.y;
    const int q0 = blockIdx.x * 64;
    const int tid = threadIdx.x;
    const int wrp = tid >> 5, lane = tid & 31;
    const long bh = (long)(b * 4 + hh) * 4096;

    // stage Q tile
    {
        const uint4* qg = (const uint4*)&g_qh[(bh + q0) * 32];
        for (int i = tid; i < 256; i += 128) {
            int row = i >> 2, ch = i & 3;
            *(uint4*)&Qs[row * 40 + ch * 8] = qg[i];
        }
    }

    const uint4* kg = (const uint4*)&g_kh[bh * 32];
    const uint4* vg = (const uint4*)&g_vh[bh * 32];
    const u32 ksmem = (u32)__cvta_generic_to_shared(&Ks[0][0]);
    const u32 vsmem = (u32)__cvta_generic_to_shared(&Vs[0][0]);
    // per-thread cp.async slots: i = tid (rows 0-31), i+128 (rows 32-63)
    const u32 off0 = (tid >> 2) * 80 + (tid & 3) * 16;
    const u32 off1 = off0 + 32 * 80;

    // prologue: issue tile 0 into buf 0
    cp16(ksmem + off0, kg + tid);
    cp16(ksmem + off1, kg + tid + 128);
    cp16(vsmem + off0, vg + tid);
    cp16(vsmem + off1, vg + tid + 128);
    asm volatile("cp.async.commit_group;");

    __syncthreads();
    // Q A-fragments (held all kernel)
    u32 qa[8];
    {
        int r = lane & 15, cc = lane >> 4;
        u32 a = (u32)__cvta_generic_to_shared(&Qs[(wrp * 16 + r) * 40 + cc * 8]);
        ldsm_x4(qa + 0, a);
        ldsm_x4(qa + 4, a + 32);
    }

    float o[4][4];
#pragma unroll
    for (int i = 0; i < 4; i++)
#pragma unroll
        for (int j = 0; j < 4; j++) o[i][j] = 0.f;
    float m0 = -1e30f, m1 = -1e30f, l0 = 0.f, l1 = 0.f;

    const u32 kaddr = (u32)__cvta_generic_to_shared(
        &Ks[0][(lane & 7) * 40 + (lane >> 3) * 8]);
    const int vm = lane >> 3;
    const u32 vaddr = (u32)__cvta_generic_to_shared(
        &Vs[0][((vm & 1) * 8 + (lane & 7)) * 40 + (vm >> 1) * 8]);

    for (int t0 = 0; t0 < 4096; t0 += 64) {
        const int buf = (t0 >> 6) & 1;
        const u32 bo = buf * 5120;
        // prefetch next tile into other buffer
        if (t0 + 64 < 4096) {
            const uint4* ks = kg + (t0 + 64) * 4;
            const uint4* vs = vg + (t0 + 64) * 4;
            const u32 nb = (buf ^ 1) * 5120;
            cp16(ksmem + nb + off0, ks + tid);
            cp16(ksmem + nb + off1, ks + tid + 128);
            cp16(vsmem + nb + off0, vs + tid);
            cp16(vsmem + nb + off1, vs + tid + 128);
        }
        asm volatile("cp.async.commit_group;");
        asm volatile("cp.async.wait_group 1;");
        __syncthreads();

        // ---- S = Q K^T
        float s[8][4];
#pragma unroll
        for (int nt = 0; nt < 8; nt++) {
            s[nt][0] = s[nt][1] = s[nt][2] = s[nt][3] = 0.f;
            u32 kb[4];
            ldsm_x4(kb, kaddr + bo + nt * 640);
            mma16816(s[nt], qa + 0, kb + 0);
            mma16816(s[nt], qa + 4, kb + 2);
        }

        // ---- online softmax (base-2, f16x2 exp)
        float mx0 = -1e30f, mx1 = -1e30f;
#pragma unroll
        for (int nt = 0; nt < 8; nt++) {
            mx0 = fmaxf(mx0, fmaxf(s[nt][0], s[nt][1]));
            mx1 = fmaxf(mx1, fmaxf(s[nt][2], s[nt][3]));
        }
        mx0 = fmaxf(mx0, __shfl_xor_sync(0xffffffffu, mx0, 1));
        mx0 = fmaxf(mx0, __shfl_xor_sync(0xffffffffu, mx0, 2));
        mx1 = fmaxf(mx1, __shfl_xor_sync(0xffffffffu, mx1, 1));
        mx1 = fmaxf(mx1, __shfl_xor_sync(0xffffffffu, mx1, 2));
        float nm0 = fmaxf(m0, mx0), nm1 = fmaxf(m1, mx1);
        float corr0 = ex2(m0 - nm0), corr1 = ex2(m1 - nm1);
        m0 = nm0; m1 = nm1;

        u32 pa[8][2];
#pragma unroll
        for (int nt = 0; nt < 8; nt++) {
            pa[nt][0] = ex2h2(packh2(s[nt][0] - m0, s[nt][1] - m0));
            pa[nt][1] = ex2h2(packh2(s[nt][2] - m1, s[nt][3] - m1));
        }
        // l-sums via shallow half2 tree then fp32
        __half2 t00 = __hadd2(__hadd2(u2h(pa[0][0]), u2h(pa[1][0])),
                              __hadd2(u2h(pa[2][0]), u2h(pa[3][0])));
        __half2 t01 = __hadd2(__hadd2(u2h(pa[4][0]), u2h(pa[5][0])),
                              __hadd2(u2h(pa[6][0]), u2h(pa[7][0])));
        __half2 t10 = __hadd2(__hadd2(u2h(pa[0][1]), u2h(pa[1][1])),
                              __hadd2(u2h(pa[2][1]), u2h(pa[3][1])));
        __half2 t11 = __hadd2(__hadd2(u2h(pa[4][1]), u2h(pa[5][1])),
                              __hadd2(u2h(pa[6][1]), u2h(pa[7][1])));
        float2 f0 = __half22float2(__hadd2(t00, t01));
        float2 f1 = __half22float2(__hadd2(t10, t11));
        l0 = l0 * corr0 + f0.x + f0.y;
        l1 = l1 * corr1 + f1.x + f1.y;
#pragma unroll
        for (int nd = 0; nd < 4; nd++) {
            o[nd][0] *= corr0; o[nd][1] *= corr0;
            o[nd][2] *= corr1; o[nd][3] *= corr1;
        }

        // ---- O += P V
#pragma unroll
        for (int kv = 0; kv < 4; kv++) {
            u32 A[4] = {pa[2 * kv][0], pa[2 * kv][1],
                        pa[2 * kv + 1][0], pa[2 * kv + 1][1]};
#pragma unroll
            for (int dh = 0; dh < 2; dh++) {
                u32 vb[4];
                ldsm_x4_t(vb, vaddr + bo + kv * 1280 + dh * 32);
                mma16816(o[2 * dh + 0], A, vb + 0);
                mma16816(o[2 * dh + 1], A, vb + 2);
            }
        }
        __syncthreads();
    }

    // ---- epilogue
    l0 += __shfl_xor_sync(0xffffffffu, l0, 1);
    l0 += __shfl_xor_sync(0xffffffffu, l0, 2);
    l1 += __shfl_xor_sync(0xffffffffu, l1, 1);
    l1 += __shfl_xor_sync(0xffffffffu, l1, 2);
    const float inv0 = 1.f / l0, inv1 = 1.f / l1;
    const int grp = lane >> 2, t4 = lane & 3;
#pragma unroll
    for (int nd = 0; nd < 4; nd++) {
        Os[(wrp * 16 + grp) * 33 + nd * 8 + 2 * t4 + 0] = o[nd][0] * inv0;
        Os[(wrp * 16 + grp) * 33 + nd * 8 + 2 * t4 + 1] = o[nd][1] * inv0;
        Os[(wrp * 16 + grp + 8) * 33 + nd * 8 + 2 * t4 + 0] = o[nd][2] * inv1;
        Os[(wrp * 16 + grp + 8) * 33 + nd * 8 + 2 * t4 + 1] = o[nd][3] * inv1;
    }
    __syncthreads();

    __half* ob = &g_aoh[(long)(b * 128 + hh * 32) * 4096 + q0];
    const int dd = tid >> 2, seg = tid & 3;
    union { __half hx[16]; uint4 ux[2]; } tmp;
#pragma unroll
    for (int i = 0; i < 16; i++)
        tmp.hx[i] = __float2half(Os[(seg * 16 + i) * 33 + dd]);
    uint4* dsth = (uint4*)&ob[dd * 4096 + seg * 16];
    dsth[0] = tmp.ux[0];
    dsth[1] = tmp.ux[1];
}

// ===========================================================================
// Kernel 3: output projection on tensor cores + bias + GN partials.
// grid (64, 2, 4), 128 threads.
// ===========================================================================
__global__ __launch_bounds__(128) void proj_kernel(const float* __restrict__ w,
                                                   const float* __restrict__ bias) {
    __shared__ __align__(16) char smemBuf[17408 + 18432];
    __half* Ws = (__half*)smemBuf;              // [64][136]
    __half* Xs = (__half*)(smemBuf + 17408);    // [128][72]
    float* Osf = (float*)smemBuf;               // overlay [64m][68]
    __shared__ float wred[4][2];

    const int b = blockIdx.z;
    const int n0 = blockIdx.x * 64;
    const int m0 = blockIdx.y * 64;
    const int tid = threadIdx.x;
    const int wrp = tid >> 5, lane = tid & 31;

    for (int idx = tid; idx < 64 * 32; idx += 128) {
        int row = idx >> 5, c4 = idx & 31;
        float4 wv = *(const float4*)&w[(m0 + row) * 128 + c4 * 4];
        *(__half2*)&Ws[row * 136 + c4 * 4 + 0] = __floats2half2_rn(wv.x, wv.y);
        *(__half2*)&Ws[row * 136 + c4 * 4 + 2] = __floats2half2_rn(wv.z, wv.w);
    }
    for (int idx = tid; idx < 128 * 8; idx += 128) {
        int row = idx >> 3, seg = idx & 7;
        *(uint4*)&Xs[row * 72 + seg * 8] =
            *(const uint4*)&g_aoh[(long)(b * 128 + row) * 4096 + n0 + seg * 8];
    }
    __syncthreads();

    float acc[8][4];
#pragma unroll
    for (int i = 0; i < 8; i++)
#pragma unroll
        for (int j = 0; j < 4; j++) acc[i][j] = 0.f;

    const u32 wsAddr = (u32)__cvta_generic_to_shared(
        &Ws[(wrp * 16 + (lane & 15)) * 136 + (lane >> 4) * 8]);
    const int vm = lane >> 3;
    const u32 xsAddr = (u32)__cvta_generic_to_shared(
        &Xs[((vm & 1) * 8 + (lane & 7)) * 72 + (vm >> 1) * 8]);

#pragma unroll
    for (int kk = 0; kk < 8; kk++) {
        u32 wa[4];
        ldsm_x4(wa, wsAddr + kk * 32);
#pragma unroll
        for (int np = 0; np < 4; np++) {
            u32 xb[4];
            ldsm_x4_t(xb, xsAddr + kk * 16 * 144 + np * 32);
            mma16816(acc[2 * np + 0], wa, xb + 0);
            mma16816(acc[2 * np + 1], wa, xb + 2);
        }
    }
    __syncthreads();   // reuse smem as Osf

    const int g = lane >> 2, t4 = lane & 3;
    const int r0 = wrp * 16 + g;
    const float b0 = bias[m0 + r0], b1 = bias[m0 + r0 + 8];
    float lsum = 0.f, lsq = 0.f;
#pragma unroll
    for (int nt = 0; nt < 8; nt++) {
        int col = nt * 8 + 2 * t4;
        float v0 = acc[nt][0] + b0, v1 = acc[nt][1] + b0;
        float v2 = acc[nt][2] + b1, v3 = acc[nt][3] + b1;
        Osf[(r0 + 0) * 68 + col + 0] = v0;
        Osf[(r0 + 0) * 68 + col + 1] = v1;
        Osf[(r0 + 8) * 68 + col + 0] = v2;
        Osf[(r0 + 8) * 68 + col + 1] = v3;
        lsum += (v0 + v1) + (v2 + v3);
        lsq = fmaf(v0, v0, lsq); lsq = fmaf(v1, v1, lsq);
        lsq = fmaf(v2, v2, lsq); lsq = fmaf(v3, v3, lsq);
    }
#pragma unroll
    for (int off = 16; off > 0; off >>= 1) {
        lsum += __shfl_xor_sync(0xffffffffu, lsum, off);
        lsq  += __shfl_xor_sync(0xffffffffu, lsq, off);
    }
    if (lane == 0) { wred[wrp][0] = lsum; wred[wrp][1] = lsq; }
    __syncthreads();
    if (tid == 0) {
        float s0 = wred[0][0] + wred[1][0], q0 = wred[0][1] + wred[1][1];
        float s1 = wred[2][0] + wred[3][0], q1 = wred[2][1] + wred[3][1];
        g_part[((b * 2 + blockIdx.y) * 64 + blockIdx.x) * 2 + 0] = make_float2(s0, q0);
        g_part[((b * 2 + blockIdx.y) * 64 + blockIdx.x) * 2 + 1] = make_float2(s1, q1);
    }

    // coalesced write of y tile
    const int mrow = tid >> 1, seg = tid & 1;
    float* dst = &g_y[(long)(b * 128 + m0 + mrow) * 4096 + n0 + seg * 32];
    const float* src = &Osf[mrow * 68 + seg * 32];
#pragma unroll
    for (int j = 0; j < 8; j++)
        *(float4*)&dst[j * 4] = *(const float4*)&src[j * 4];
}

// ===========================================================================
// Kernel 3b: reduce GN partials. grid (4,4), 64 threads.
// ===========================================================================
__global__ void stats_kernel() {
    const int gg = blockIdx.x, b = blockIdx.y;
    const int by = gg >> 1, gl = gg & 1;
    const int t = threadIdx.x;
    float2 pv = g_part[((b * 2 + by) * 64 + t) * 2 + gl];
    float s = pv.x, ss = pv.y;
#pragma unroll
    for (int off = 16; off > 0; off >>= 1) {
        s  += __shfl_xor_sync(0xffffffffu, s, off);
        ss += __shfl_xor_sync(0xffffffffu, ss, off);
    }
    __shared__ float2 w2[2];
    if ((t & 31) == 0) w2[t >> 5] = make_float2(s, ss);
    __syncthreads();
    if (t == 0) {
        s = w2[0].x + w2[1].x;
        ss = w2[0].y + w2[1].y;
        const float invn = 1.f / 131072.f;
        float mean = s * invn;
        float var = ss * invn - mean * mean;
        g_stats[b * 4 + gg] = make_float2(mean, rsqrtf(var + GN_EPS));
    }
}

// ===========================================================================
// Kernel 4: GroupNorm affine + residual.
// ===========================================================================
__global__ __launch_bounds__(256) void norm_kernel(const float* __restrict__ x,
                                                   const float* __restrict__ gamma,
                                                   const float* __restrict__ beta,
                                                   float* __restrict__ out) {
    const int i4 = blockIdx.x * 256 + threadIdx.x;
    const int e = i4 * 4;
    const int c = (e >> 12) & 127;
    const int b = e >> 19;
    float2 st = g_stats[b * 4 + (c >> 5)];
    float ga = gamma[c] * st.y;
    float be = beta[c] - st.x * ga;
    float4 yv = *(const float4*)&g_y[e];
    float4 xv = *(const float4*)&x[e];
    float4 r;
    r.x = fmaf(yv.x, ga, be) + xv.x;
    r.y = fmaf(yv.y, ga, be) + xv.y;
    r.z = fmaf(yv.z, ga, be) + xv.z;
    r.w = fmaf(yv.w, ga, be) + xv.w;
    *(float4*)&out[e] = r;
}

// ===========================================================================
extern "C" void kernel_launch(void* const* d_in, const int* in_sizes, int n_in,
                              void* d_out, int out_size) {
    const float* x      = (const float*)d_in[0];
    const float* w_qkv  = (const float*)d_in[1];
    const float* w_out  = (const float*)d_in[2];
    const float* b_out  = (const float*)d_in[3];
    const float* gammap = (const float*)d_in[4];
    const float* betap  = (const float*)d_in[5];
    float* out = (float*)d_out;

    cvt_kernel<<<2048, 256>>>(x);
    qkv_kernel<<<dim3(64, 6, 4), 128>>>(w_qkv);
    attn_kernel<<<dim3(64, 4, 4), 128>>>();
    proj_kernel<<<dim3(64, 2, 4), 128>>>(w_out, b_out);
    stats_kernel<<<dim3(4, 4), 64>>>();
    norm_kernel<<<2048, 256>>>(x, gammap, betap, out);
}

// round 7
// speedup vs baseline: 8.1735x; 1.0002x over previous
#include <cuda_runtime.h>
#include <cuda_fp16.h>

typedef unsigned int u32;

#define GN_EPS 1e-5f
// (1/sqrt(32)) * log2(e): softmax runs in base-2 domain
#define QSCALE 0.25501817097393111f

// ---------------- scratch (static device allocations, allowed) -------------
__device__ __align__(16) __half g_xh[4 * 128 * 4096];    // x in fp16 [b][c][n]
__device__ __align__(16) __half g_qh[4 * 4 * 4096 * 32]; // [b][h][n][d]
__device__ __align__(16) __half g_kh[4 * 4 * 4096 * 32];
__device__ __align__(16) __half g_vh[4 * 4 * 4096 * 32];
__device__ __align__(16) __half g_aoh[4 * 128 * 4096];   // attn out fp16 [b][c][n]
__device__ __align__(16) float g_y[4 * 128 * 4096];      // proj out fp32 [b][c][n]
__device__ float2 g_part[4 * 2 * 64 * 2];
__device__ float2 g_stats[16];

// ---------------- PTX helpers ----------------------------------------------
__device__ __forceinline__ float ex2(float x) {
    float r; asm("ex2.approx.ftz.f32 %0, %1;" : "=f"(r) : "f"(x)); return r;
}
__device__ __forceinline__ u32 ex2h2(u32 x) {
    u32 r; asm("ex2.approx.f16x2 %0, %1;" : "=r"(r) : "r"(x)); return r;
}
__device__ __forceinline__ void ldsm_x4(u32* r, u32 addr) {
    asm volatile("ldmatrix.sync.aligned.m8n8.x4.shared.b16 {%0,%1,%2,%3}, [%4];"
                 : "=r"(r[0]), "=r"(r[1]), "=r"(r[2]), "=r"(r[3]) : "r"(addr));
}
__device__ __forceinline__ void ldsm_x4_t(u32* r, u32 addr) {
    asm volatile("ldmatrix.sync.aligned.m8n8.x4.trans.shared.b16 {%0,%1,%2,%3}, [%4];"
                 : "=r"(r[0]), "=r"(r[1]), "=r"(r[2]), "=r"(r[3]) : "r"(addr));
}
__device__ __forceinline__ void mma16816(float* c, const u32* a, const u32* b) {
    asm volatile("mma.sync.aligned.m16n8k16.row.col.f32.f16.f16.f32 "
                 "{%0,%1,%2,%3}, {%4,%5,%6,%7}, {%8,%9}, {%0,%1,%2,%3};"
                 : "+f"(c[0]), "+f"(c[1]), "+f"(c[2]), "+f"(c[3])
                 : "r"(a[0]), "r"(a[1]), "r"(a[2]), "r"(a[3]), "r"(b[0]), "r"(b[1]));
}
__device__ __forceinline__ u32 packh2(float a, float b) {
    __half2 h = __floats2half2_rn(a, b);
    return *(u32*)&h;
}
__device__ __forceinline__ __half2 u2h(u32 x) { __half2 h; *(u32*)&h = x; return h; }
__device__ __forceinline__ void cp16(u32 smem, const void* gmem) {
    asm volatile("cp.async.cg.shared.global [%0], [%1], 16;" :: "r"(smem), "l"(gmem));
}

// ===========================================================================
// Kernel 0: convert x fp32 -> fp16
// ===========================================================================
__global__ __launch_bounds__(256) void cvt_kernel(const float* __restrict__ x) {
    const int i = blockIdx.x * 256 + threadIdx.x;  // 524288 float4s
    float4 v = *(const float4*)&x[i * 4];
    *(__half2*)&g_xh[i * 4 + 0] = __floats2half2_rn(v.x, v.y);
    *(__half2*)&g_xh[i * 4 + 2] = __floats2half2_rn(v.z, v.w);
}

// ===========================================================================
// Kernel 1: QKV projection on tensor cores.
// out[m,n] = sum_k W[m,k] * x[k,n].  Tile 64(m) x 64(n), k=128.
// grid (64, 6, 4), 128 threads (4 warps, 16 m-rows each).
// ===========================================================================
__global__ __launch_bounds__(128) void qkv_kernel(const float* __restrict__ w) {
    __shared__ __align__(16) char smemBuf[17408 + 18432];
    __half* Ws = (__half*)smemBuf;                 // [64][136]
    __half* Xs = (__half*)(smemBuf + 17408);       // [128][72]
    __half* Osh = (__half*)smemBuf;                // overlay after mainloop [64n][72]

    const int b = blockIdx.z;
    const int n0 = blockIdx.x * 64;
    const int m0 = blockIdx.y * 64;
    const int tid = threadIdx.x;
    const int wrp = tid >> 5, lane = tid & 31;

    // stage W (fp32 -> fp16), 64x128
    for (int idx = tid; idx < 64 * 32; idx += 128) {
        int row = idx >> 5, c4 = idx & 31;
        float4 wv = *(const float4*)&w[(m0 + row) * 128 + c4 * 4];
        *(__half2*)&Ws[row * 136 + c4 * 4 + 0] = __floats2half2_rn(wv.x, wv.y);
        *(__half2*)&Ws[row * 136 + c4 * 4 + 2] = __floats2half2_rn(wv.z, wv.w);
    }
    // stage X tile [k=128][n=64] fp16
    for (int idx = tid; idx < 128 * 8; idx += 128) {
        int row = idx >> 3, seg = idx & 7;
        *(uint4*)&Xs[row * 72 + seg * 8] =
            *(const uint4*)&g_xh[(b * 128 + row) * 4096 + n0 + seg * 8];
    }
    __syncthreads();

    float acc[8][4];
#pragma unroll
    for (int i = 0; i < 8; i++)
#pragma unroll
        for (int j = 0; j < 4; j++) acc[i][j] = 0.f;

    const u32 wsAddr = (u32)__cvta_generic_to_shared(
        &Ws[(wrp * 16 + (lane & 15)) * 136 + (lane >> 4) * 8]);
    const int vm = lane >> 3;
    const u32 xsAddr = (u32)__cvta_generic_to_shared(
        &Xs[((vm & 1) * 8 + (lane & 7)) * 72 + (vm >> 1) * 8]);

#pragma unroll
    for (int kk = 0; kk < 8; kk++) {
        u32 wa[4];
        ldsm_x4(wa, wsAddr + kk * 32);
#pragma unroll
        for (int np = 0; np < 4; np++) {
            u32 xb[4];
            ldsm_x4_t(xb, xsAddr + kk * 16 * 144 + np * 32);
            mma16816(acc[2 * np + 0], wa, xb + 0);
            mma16816(acc[2 * np + 1], wa, xb + 2);
        }
    }
    __syncthreads();   // done with Ws/Xs, reuse as Osh

    const float sc = (m0 < 128) ? QSCALE : 1.0f;
    const int g = lane >> 2, t4 = lane & 3;
#pragma unroll
    for (int nt = 0; nt < 8; nt++) {
        int col = nt * 8 + 2 * t4;
        int r0 = wrp * 16 + g;
        Osh[(col + 0) * 72 + r0 + 0] = __float2half(acc[nt][0] * sc);
        Osh[(col + 1) * 72 + r0 + 0] = __float2half(acc[nt][1] * sc);
        Osh[(col + 0) * 72 + r0 + 8] = __float2half(acc[nt][2] * sc);
        Osh[(col + 1) * 72 + r0 + 8] = __float2half(acc[nt][3] * sc);
    }
    __syncthreads();

    const int which = m0 >> 7;
    __half* dstbase = (which == 0) ? g_qh : ((which == 1) ? g_kh : g_vh);
    const int h0 = (m0 >> 5) & 3;
    const int n = tid >> 1, hi = tid & 1;
    __half* dst = &dstbase[((long)(b * 4 + h0 + hi) * 4096 + n0 + n) * 32];
    const __half* src = &Osh[n * 72 + hi * 32];
    *(uint4*)&dst[0]  = *(const uint4*)&src[0];
    *(uint4*)&dst[8]  = *(const uint4*)&src[8];
    *(uint4*)&dst[16] = *(const uint4*)&src[16];
    *(uint4*)&dst[24] = *(const uint4*)&src[24];
}

// ===========================================================================
// Kernel 2: fp16 tensor-core flash attention, cp.async double-buffered KV,
// f16x2 exp2.  grid (64, 4, 4), 128 threads.
// ===========================================================================
__global__ __launch_bounds__(128) void attn_kernel() {
    __shared__ __align__(16) __half Qs[64 * 40];
    __shared__ __align__(16) __half Ks[2][64 * 40];
    __shared__ __align__(16) __half Vs[2][64 * 40];
    __shared__ __align__(16) float Os[64 * 33];

    const int b = blockIdx.z, hh = blockIdx.y;
    const int q0 = blockIdx.x * 64;
    const int tid = threadIdx.x;
    const int wrp = tid >> 5, lane = tid & 31;
    const long bh = (long)(b * 4 + hh) * 4096;

    // stage Q tile
    {
        const uint4* qg = (const uint4*)&g_qh[(bh + q0) * 32];
        for (int i = tid; i < 256; i += 128) {
            int row = i >> 2, ch = i & 3;
            *(uint4*)&Qs[row * 40 + ch * 8] = qg[i];
        }
    }

    const uint4* kg = (const uint4*)&g_kh[bh * 32];
    const uint4* vg = (const uint4*)&g_vh[bh * 32];
    const u32 ksmem = (u32)__cvta_generic_to_shared(&Ks[0][0]);
    const u32 vsmem = (u32)__cvta_generic_to_shared(&Vs[0][0]);
    // per-thread cp.async slots: i = tid (rows 0-31), i+128 (rows 32-63)
    const u32 off0 = (tid >> 2) * 80 + (tid & 3) * 16;
    const u32 off1 = off0 + 32 * 80;

    // prologue: issue tile 0 into buf 0
    cp16(ksmem + off0, kg + tid);
    cp16(ksmem + off1, kg + tid + 128);
    cp16(vsmem + off0, vg + tid);
    cp16(vsmem + off1, vg + tid + 128);
    asm volatile("cp.async.commit_group;");

    __syncthreads();
    // Q A-fragments (held all kernel)
    u32 qa[8];
    {
        int r = lane & 15, cc = lane >> 4;
        u32 a = (u32)__cvta_generic_to_shared(&Qs[(wrp * 16 + r) * 40 + cc * 8]);
        ldsm_x4(qa + 0, a);
        ldsm_x4(qa + 4, a + 32);
    }

    float o[4][4];
#pragma unroll
    for (int i = 0; i < 4; i++)
#pragma unroll
        for (int j = 0; j < 4; j++) o[i][j] = 0.f;
    float m0 = -1e30f, m1 = -1e30f, l0 = 0.f, l1 = 0.f;

    const u32 kaddr = (u32)__cvta_generic_to_shared(
        &Ks[0][(lane & 7) * 40 + (lane >> 3) * 8]);
    const int vm = lane >> 3;
    const u32 vaddr = (u32)__cvta_generic_to_shared(
        &Vs[0][((vm & 1) * 8 + (lane & 7)) * 40 + (vm >> 1) * 8]);

    for (int t0 = 0; t0 < 4096; t0 += 64) {
        const int buf = (t0 >> 6) & 1;
        const u32 bo = buf * 5120;
        // prefetch next tile into other buffer
        if (t0 + 64 < 4096) {
            const uint4* ks = kg + (t0 + 64) * 4;
            const uint4* vs = vg + (t0 + 64) * 4;
            const u32 nb = (buf ^ 1) * 5120;
            cp16(ksmem + nb + off0, ks + tid);
            cp16(ksmem + nb + off1, ks + tid + 128);
            cp16(vsmem + nb + off0, vs + tid);
            cp16(vsmem + nb + off1, vs + tid + 128);
        }
        asm volatile("cp.async.commit_group;");
        asm volatile("cp.async.wait_group 1;");
        __syncthreads();

        // ---- S = Q K^T
        float s[8][4];
#pragma unroll
        for (int nt = 0; nt < 8; nt++) {
            s[nt][0] = s[nt][1] = s[nt][2] = s[nt][3] = 0.f;
            u32 kb[4];
            ldsm_x4(kb, kaddr + bo + nt * 640);
            mma16816(s[nt], qa + 0, kb + 0);
            mma16816(s[nt], qa + 4, kb + 2);
        }

        // ---- online softmax (base-2, f16x2 exp)
        float mx0 = -1e30f, mx1 = -1e30f;
#pragma unroll
        for (int nt = 0; nt < 8; nt++) {
            mx0 = fmaxf(mx0, fmaxf(s[nt][0], s[nt][1]));
            mx1 = fmaxf(mx1, fmaxf(s[nt][2], s[nt][3]));
        }
        mx0 = fmaxf(mx0, __shfl_xor_sync(0xffffffffu, mx0, 1));
        mx0 = fmaxf(mx0, __shfl_xor_sync(0xffffffffu, mx0, 2));
        mx1 = fmaxf(mx1, __shfl_xor_sync(0xffffffffu, mx1, 1));
        mx1 = fmaxf(mx1, __shfl_xor_sync(0xffffffffu, mx1, 2));
        float nm0 = fmaxf(m0, mx0), nm1 = fmaxf(m1, mx1);
        float corr0 = ex2(m0 - nm0), corr1 = ex2(m1 - nm1);
        m0 = nm0; m1 = nm1;

        u32 pa[8][2];
#pragma unroll
        for (int nt = 0; nt < 8; nt++) {
            pa[nt][0] = ex2h2(packh2(s[nt][0] - m0, s[nt][1] - m0));
            pa[nt][1] = ex2h2(packh2(s[nt][2] - m1, s[nt][3] - m1));
        }
        // l-sums via shallow half2 tree then fp32
        __half2 t00 = __hadd2(__hadd2(u2h(pa[0][0]), u2h(pa[1][0])),
                              __hadd2(u2h(pa[2][0]), u2h(pa[3][0])));
        __half2 t01 = __hadd2(__hadd2(u2h(pa[4][0]), u2h(pa[5][0])),
                              __hadd2(u2h(pa[6][0]), u2h(pa[7][0])));
        __half2 t10 = __hadd2(__hadd2(u2h(pa[0][1]), u2h(pa[1][1])),
                              __hadd2(u2h(pa[2][1]), u2h(pa[3][1])));
        __half2 t11 = __hadd2(__hadd2(u2h(pa[4][1]), u2h(pa[5][1])),
                              __hadd2(u2h(pa[6][1]), u2h(pa[7][1])));
        float2 f0 = __half22float2(__hadd2(t00, t01));
        float2 f1 = __half22float2(__hadd2(t10, t11));
        l0 = l0 * corr0 + f0.x + f0.y;
        l1 = l1 * corr1 + f1.x + f1.y;
#pragma unroll
        for (int nd = 0; nd < 4; nd++) {
            o[nd][0] *= corr0; o[nd][1] *= corr0;
            o[nd][2] *= corr1; o[nd][3] *= corr1;
        }

        // ---- O += P V
#pragma unroll
        for (int kv = 0; kv < 4; kv++) {
            u32 A[4] = {pa[2 * kv][0], pa[2 * kv][1],
                        pa[2 * kv + 1][0], pa[2 * kv + 1][1]};
#pragma unroll
            for (int dh = 0; dh < 2; dh++) {
                u32 vb[4];
                ldsm_x4_t(vb, vaddr + bo + kv * 1280 + dh * 32);
                mma16816(o[2 * dh + 0], A, vb + 0);
                mma16816(o[2 * dh + 1], A, vb + 2);
            }
        }
        __syncthreads();
    }

    // ---- epilogue
    l0 += __shfl_xor_sync(0xffffffffu, l0, 1);
    l0 += __shfl_xor_sync(0xffffffffu, l0, 2);
    l1 += __shfl_xor_sync(0xffffffffu, l1, 1);
    l1 += __shfl_xor_sync(0xffffffffu, l1, 2);
    const float inv0 = 1.f / l0, inv1 = 1.f / l1;
    const int grp = lane >> 2, t4 = lane & 3;
#pragma unroll
    for (int nd = 0; nd < 4; nd++) {
        Os[(wrp * 16 + grp) * 33 + nd * 8 + 2 * t4 + 0] = o[nd][0] * inv0;
        Os[(wrp * 16 + grp) * 33 + nd * 8 + 2 * t4 + 1] = o[nd][1] * inv0;
        Os[(wrp * 16 + grp + 8) * 33 + nd * 8 + 2 * t4 + 0] = o[nd][2] * inv1;
        Os[(wrp * 16 + grp + 8) * 33 + nd * 8 + 2 * t4 + 1] = o[nd][3] * inv1;
    }
    __syncthreads();

    __half* ob = &g_aoh[(long)(b * 128 + hh * 32) * 4096 + q0];
    const int dd = tid >> 2, seg = tid & 3;
    union { __half hx[16]; uint4 ux[2]; } tmp;
#pragma unroll
    for (int i = 0; i < 16; i++)
        tmp.hx[i] = __float2half(Os[(seg * 16 + i) * 33 + dd]);
    uint4* dsth = (uint4*)&ob[dd * 4096 + seg * 16];
    dsth[0] = tmp.ux[0];
    dsth[1] = tmp.ux[1];
}

// ===========================================================================
// Kernel 3: output projection on tensor cores + bias + GN partials.
// grid (64, 2, 4), 128 threads.
// ===========================================================================
__global__ __launch_bounds__(128) void proj_kernel(const float* __restrict__ w,
                                                   const float* __restrict__ bias) {
    __shared__ __align__(16) char smemBuf[17408 + 18432];
    __half* Ws = (__half*)smemBuf;              // [64][136]
    __half* Xs = (__half*)(smemBuf + 17408);    // [128][72]
    float* Osf = (float*)smemBuf;               // overlay [64m][68]
    __shared__ float wred[4][2];

    const int b = blockIdx.z;
    const int n0 = blockIdx.x * 64;
    const int m0 = blockIdx.y * 64;
    const int tid = threadIdx.x;
    const int wrp = tid >> 5, lane = tid & 31;

    for (int idx = tid; idx < 64 * 32; idx += 128) {
        int row = idx >> 5, c4 = idx & 31;
        float4 wv = *(const float4*)&w[(m0 + row) * 128 + c4 * 4];
        *(__half2*)&Ws[row * 136 + c4 * 4 + 0] = __floats2half2_rn(wv.x, wv.y);
        *(__half2*)&Ws[row * 136 + c4 * 4 + 2] = __floats2half2_rn(wv.z, wv.w);
    }
    for (int idx = tid; idx < 128 * 8; idx += 128) {
        int row = idx >> 3, seg = idx & 7;
        *(uint4*)&Xs[row * 72 + seg * 8] =
            *(const uint4*)&g_aoh[(long)(b * 128 + row) * 4096 + n0 + seg * 8];
    }
    __syncthreads();

    float acc[8][4];
#pragma unroll
    for (int i = 0; i < 8; i++)
#pragma unroll
        for (int j = 0; j < 4; j++) acc[i][j] = 0.f;

    const u32 wsAddr = (u32)__cvta_generic_to_shared(
        &Ws[(wrp * 16 + (lane & 15)) * 136 + (lane >> 4) * 8]);
    const int vm = lane >> 3;
    const u32 xsAddr = (u32)__cvta_generic_to_shared(
        &Xs[((vm & 1) * 8 + (lane & 7)) * 72 + (vm >> 1) * 8]);

#pragma unroll
    for (int kk = 0; kk < 8; kk++) {
        u32 wa[4];
        ldsm_x4(wa, wsAddr + kk * 32);
#pragma unroll
        for (int np = 0; np < 4; np++) {
            u32 xb[4];
            ldsm_x4_t(xb, xsAddr + kk * 16 * 144 + np * 32);
            mma16816(acc[2 * np + 0], wa, xb + 0);
            mma16816(acc[2 * np + 1], wa, xb + 2);
        }
    }
    __syncthreads();   // reuse smem as Osf

    const int g = lane >> 2, t4 = lane & 3;
    const int r0 = wrp * 16 + g;
    const float b0 = bias[m0 + r0], b1 = bias[m0 + r0 + 8];
    float lsum = 0.f, lsq = 0.f;
#pragma unroll
    for (int nt = 0; nt < 8; nt++) {
        int col = nt * 8 + 2 * t4;
        float v0 = acc[nt][0] + b0, v1 = acc[nt][1] + b0;
        float v2 = acc[nt][2] + b1, v3 = acc[nt][3] + b1;
        Osf[(r0 + 0) * 68 + col + 0] = v0;
        Osf[(r0 + 0) * 68 + col + 1] = v1;
        Osf[(r0 + 8) * 68 + col + 0] = v2;
        Osf[(r0 + 8) * 68 + col + 1] = v3;
        lsum += (v0 + v1) + (v2 + v3);
        lsq = fmaf(v0, v0, lsq); lsq = fmaf(v1, v1, lsq);
        lsq = fmaf(v2, v2, lsq); lsq = fmaf(v3, v3, lsq);
    }
#pragma unroll
    for (int off = 16; off > 0; off >>= 1) {
        lsum += __shfl_xor_sync(0xffffffffu, lsum, off);
        lsq  += __shfl_xor_sync(0xffffffffu, lsq, off);
    }
    if (lane == 0) { wred[wrp][0] = lsum; wred[wrp][1] = lsq; }
    __syncthreads();
    if (tid == 0) {
        float s0 = wred[0][0] + wred[1][0], q0 = wred[0][1] + wred[1][1];
        float s1 = wred[2][0] + wred[3][0], q1 = wred[2][1] + wred[3][1];
        g_part[((b * 2 + blockIdx.y) * 64 + blockIdx.x) * 2 + 0] = make_float2(s0, q0);
        g_part[((b * 2 + blockIdx.y) * 64 + blockIdx.x) * 2 + 1] = make_float2(s1, q1);
    }

    // coalesced write of y tile
    const int mrow = tid >> 1, seg = tid & 1;
    float* dst = &g_y[(long)(b * 128 + m0 + mrow) * 4096 + n0 + seg * 32];
    const float* src = &Osf[mrow * 68 + seg * 32];
#pragma unroll
    for (int j = 0; j < 8; j++)
        *(float4*)&dst[j * 4] = *(const float4*)&src[j * 4];
}

// ===========================================================================
// Kernel 3b: reduce GN partials. grid (4,4), 64 threads.
// ===========================================================================
__global__ void stats_kernel() {
    const int gg = blockIdx.x, b = blockIdx.y;
    const int by = gg >> 1, gl = gg & 1;
    const int t = threadIdx.x;
    float2 pv = g_part[((b * 2 + by) * 64 + t) * 2 + gl];
    float s = pv.x, ss = pv.y;
#pragma unroll
    for (int off = 16; off > 0; off >>= 1) {
        s  += __shfl_xor_sync(0xffffffffu, s, off);
        ss += __shfl_xor_sync(0xffffffffu, ss, off);
    }
    __shared__ float2 w2[2];
    if ((t & 31) == 0) w2[t >> 5] = make_float2(s, ss);
    __syncthreads();
    if (t == 0) {
        s = w2[0].x + w2[1].x;
        ss = w2[0].y + w2[1].y;
        const float invn = 1.f / 131072.f;
        float mean = s * invn;
        float var = ss * invn - mean * mean;
        g_stats[b * 4 + gg] = make_float2(mean, rsqrtf(var + GN_EPS));
    }
}

// ===========================================================================
// Kernel 4: GroupNorm affine + residual.
// ===========================================================================
__global__ __launch_bounds__(256) void norm_kernel(const float* __restrict__ x,
                                                   const float* __restrict__ gamma,
                                                   const float* __restrict__ beta,
                                                   float* __restrict__ out) {
    const int i4 = blockIdx.x * 256 + threadIdx.x;
    const int e = i4 * 4;
    const int c = (e >> 12) & 127;
    const int b = e >> 19;
    float2 st = g_stats[b * 4 + (c >> 5)];
    float ga = gamma[c] * st.y;
    float be = beta[c] - st.x * ga;
    float4 yv = *(const float4*)&g_y[e];
    float4 xv = *(const float4*)&x[e];
    float4 r;
    r.x = fmaf(yv.x, ga, be) + xv.x;
    r.y = fmaf(yv.y, ga, be) + xv.y;
    r.z = fmaf(yv.z, ga, be) + xv.z;
    r.w = fmaf(yv.w, ga, be) + xv.w;
    *(float4*)&out[e] = r;
}

// ===========================================================================
extern "C" void kernel_launch(void* const* d_in, const int* in_sizes, int n_in,
                              void* d_out, int out_size) {
    const float* x      = (const float*)d_in[0];
    const float* w_qkv  = (const float*)d_in[1];
    const float* w_out  = (const float*)d_in[2];
    const float* b_out  = (const float*)d_in[3];
    const float* gammap = (const float*)d_in[4];
    const float* betap  = (const float*)d_in[5];
    float* out = (float*)d_out;

    cvt_kernel<<<2048, 256>>>(x);
    qkv_kernel<<<dim3(64, 6, 4), 128>>>(w_qkv);
    attn_kernel<<<dim3(64, 4, 4), 128>>>();
    proj_kernel<<<dim3(64, 2, 4), 128>>>(w_out, b_out);
    stats_kernel<<<dim3(4, 4), 64>>>();
    norm_kernel<<<2048, 256>>>(x, gammap, betap, out);
}

// round 8
// speedup vs baseline: 8.2463x; 1.0089x over previous
#include <cuda_runtime.h>
#include <cuda_fp16.h>

typedef unsigned int u32;

#define GN_EPS 1e-5f
// (1/sqrt(32)) * log2(e): softmax runs in base-2 domain
#define QSCALE 0.25501817097393111f

// ---------------- scratch (static device allocations, allowed) -------------
__device__ __align__(16) __half g_xh[4 * 128 * 4096];    // x in fp16 [b][c][n]
__device__ __align__(16) __half g_qh[4 * 4 * 4096 * 32]; // [b][h][n][d]
__device__ __align__(16) __half g_kh[4 * 4 * 4096 * 32];
__device__ __align__(16) __half g_vh[4 * 4 * 4096 * 32];
__device__ __align__(16) __half g_aoh[4 * 128 * 4096];   // attn out fp16 [b][c][n]
__device__ __align__(16) float g_y[4 * 128 * 4096];      // proj out fp32 [b][c][n]
__device__ float2 g_part[4 * 2 * 64 * 2];
__device__ float2 g_stats[16];

// ---------------- PTX helpers ----------------------------------------------
__device__ __forceinline__ float ex2(float x) {
    float r; asm("ex2.approx.ftz.f32 %0, %1;" : "=f"(r) : "f"(x)); return r;
}
__device__ __forceinline__ u32 ex2h2(u32 x) {
    u32 r; asm("ex2.approx.f16x2 %0, %1;" : "=r"(r) : "r"(x)); return r;
}
__device__ __forceinline__ void ldsm_x4(u32* r, u32 addr) {
    asm volatile("ldmatrix.sync.aligned.m8n8.x4.shared.b16 {%0,%1,%2,%3}, [%4];"
                 : "=r"(r[0]), "=r"(r[1]), "=r"(r[2]), "=r"(r[3]) : "r"(addr));
}
__device__ __forceinline__ void ldsm_x4_t(u32* r, u32 addr) {
    asm volatile("ldmatrix.sync.aligned.m8n8.x4.trans.shared.b16 {%0,%1,%2,%3}, [%4];"
                 : "=r"(r[0]), "=r"(r[1]), "=r"(r[2]), "=r"(r[3]) : "r"(addr));
}
__device__ __forceinline__ void mma16816(float* c, const u32* a, const u32* b) {
    asm volatile("mma.sync.aligned.m16n8k16.row.col.f32.f16.f16.f32 "
                 "{%0,%1,%2,%3}, {%4,%5,%6,%7}, {%8,%9}, {%0,%1,%2,%3};"
                 : "+f"(c[0]), "+f"(c[1]), "+f"(c[2]), "+f"(c[3])
                 : "r"(a[0]), "r"(a[1]), "r"(a[2]), "r"(a[3]), "r"(b[0]), "r"(b[1]));
}
__device__ __forceinline__ u32 packh2(float a, float b) {
    __half2 h = __floats2half2_rn(a, b);
    return *(u32*)&h;
}
__device__ __forceinline__ __half2 u2h(u32 x) { __half2 h; *(u32*)&h = x; return h; }
__device__ __forceinline__ void cp16(u32 smem, const void* gmem) {
    asm volatile("cp.async.cg.shared.global [%0], [%1], 16;" :: "r"(smem), "l"(gmem));
}

// ===========================================================================
// Kernel 0: convert x fp32 -> fp16
// ===========================================================================
__global__ __launch_bounds__(256) void cvt_kernel(const float* __restrict__ x) {
    const int i = blockIdx.x * 256 + threadIdx.x;  // 524288 float4s
    float4 v = *(const float4*)&x[i * 4];
    *(__half2*)&g_xh[i * 4 + 0] = __floats2half2_rn(v.x, v.y);
    *(__half2*)&g_xh[i * 4 + 2] = __floats2half2_rn(v.z, v.w);
}

// ===========================================================================
// Kernel 1: QKV projection on tensor cores.
// out[m,n] = sum_k W[m,k] * x[k,n].  Tile 64(m) x 64(n), k=128.
// grid (64, 6, 4), 128 threads (4 warps, 16 m-rows each).
// ===========================================================================
__global__ __launch_bounds__(128) void qkv_kernel(const float* __restrict__ w) {
    __shared__ __align__(16) char smemBuf[17408 + 18432];
    __half* Ws = (__half*)smemBuf;                 // [64][136]
    __half* Xs = (__half*)(smemBuf + 17408);       // [128][72]
    __half* Osh = (__half*)smemBuf;                // overlay after mainloop [64n][72]

    const int b = blockIdx.z;
    const int n0 = blockIdx.x * 64;
    const int m0 = blockIdx.y * 64;
    const int tid = threadIdx.x;
    const int wrp = tid >> 5, lane = tid & 31;

    // stage W (fp32 -> fp16), 64x128
    for (int idx = tid; idx < 64 * 32; idx += 128) {
        int row = idx >> 5, c4 = idx & 31;
        float4 wv = *(const float4*)&w[(m0 + row) * 128 + c4 * 4];
        *(__half2*)&Ws[row * 136 + c4 * 4 + 0] = __floats2half2_rn(wv.x, wv.y);
        *(__half2*)&Ws[row * 136 + c4 * 4 + 2] = __floats2half2_rn(wv.z, wv.w);
    }
    // stage X tile [k=128][n=64] fp16
    for (int idx = tid; idx < 128 * 8; idx += 128) {
        int row = idx >> 3, seg = idx & 7;
        *(uint4*)&Xs[row * 72 + seg * 8] =
            *(const uint4*)&g_xh[(b * 128 + row) * 4096 + n0 + seg * 8];
    }
    __syncthreads();

    float acc[8][4];
#pragma unroll
    for (int i = 0; i < 8; i++)
#pragma unroll
        for (int j = 0; j < 4; j++) acc[i][j] = 0.f;

    const u32 wsAddr = (u32)__cvta_generic_to_shared(
        &Ws[(wrp * 16 + (lane & 15)) * 136 + (lane >> 4) * 8]);
    const int vm = lane >> 3;
    const u32 xsAddr = (u32)__cvta_generic_to_shared(
        &Xs[((vm & 1) * 8 + (lane & 7)) * 72 + (vm >> 1) * 8]);

#pragma unroll
    for (int kk = 0; kk < 8; kk++) {
        u32 wa[4];
        ldsm_x4(wa, wsAddr + kk * 32);
#pragma unroll
        for (int np = 0; np < 4; np++) {
            u32 xb[4];
            ldsm_x4_t(xb, xsAddr + kk * 16 * 144 + np * 32);
            mma16816(acc[2 * np + 0], wa, xb + 0);
            mma16816(acc[2 * np + 1], wa, xb + 2);
        }
    }
    __syncthreads();   // done with Ws/Xs, reuse as Osh

    const float sc = (m0 < 128) ? QSCALE : 1.0f;
    const int g = lane >> 2, t4 = lane & 3;
#pragma unroll
    for (int nt = 0; nt < 8; nt++) {
        int col = nt * 8 + 2 * t4;
        int r0 = wrp * 16 + g;
        Osh[(col + 0) * 72 + r0 + 0] = __float2half(acc[nt][0] * sc);
        Osh[(col + 1) * 72 + r0 + 0] = __float2half(acc[nt][1] * sc);
        Osh[(col + 0) * 72 + r0 + 8] = __float2half(acc[nt][2] * sc);
        Osh[(col + 1) * 72 + r0 + 8] = __float2half(acc[nt][3] * sc);
    }
    __syncthreads();

    const int which = m0 >> 7;
    __half* dstbase = (which == 0) ? g_qh : ((which == 1) ? g_kh : g_vh);
    const int h0 = (m0 >> 5) & 3;
    const int n = tid >> 1, hi = tid & 1;
    __half* dst = &dstbase[((long)(b * 4 + h0 + hi) * 4096 + n0 + n) * 32];
    const __half* src = &Osh[n * 72 + hi * 32];
    *(uint4*)&dst[0]  = *(const uint4*)&src[0];
    *(uint4*)&dst[8]  = *(const uint4*)&src[8];
    *(uint4*)&dst[16] = *(const uint4*)&src[16];
    *(uint4*)&dst[24] = *(const uint4*)&src[24];
}

// ===========================================================================
// Kernel 2: fp16 tensor-core flash attention, cp.async double-buffered KV,
// f16x2 exp2.  grid (64, 4, 4), 128 threads.
// ===========================================================================
__global__ __launch_bounds__(128) void attn_kernel() {
    __shared__ __align__(16) __half Qs[64 * 40];
    __shared__ __align__(16) __half Ks[2][64 * 40];
    __shared__ __align__(16) __half Vs[2][64 * 40];
    __shared__ __align__(16) float Os[64 * 33];

    const int b = blockIdx.z, hh = blockIdx.y;
    const int q0 = blockIdx.x * 64;
    const int tid = threadIdx.x;
    const int wrp = tid >> 5, lane = tid & 31;
    const long bh = (long)(b * 4 + hh) * 4096;

    // stage Q tile
    {
        const uint4* qg = (const uint4*)&g_qh[(bh + q0) * 32];
        for (int i = tid; i < 256; i += 128) {
            int row = i >> 2, ch = i & 3;
            *(uint4*)&Qs[row * 40 + ch * 8] = qg[i];
        }
    }

    const uint4* kg = (const uint4*)&g_kh[bh * 32];
    const uint4* vg = (const uint4*)&g_vh[bh * 32];
    const u32 ksmem = (u32)__cvta_generic_to_shared(&Ks[0][0]);
    const u32 vsmem = (u32)__cvta_generic_to_shared(&Vs[0][0]);
    // per-thread cp.async slots: i = tid (rows 0-31), i+128 (rows 32-63)
    const u32 off0 = (tid >> 2) * 80 + (tid & 3) * 16;
    const u32 off1 = off0 + 32 * 80;

    // prologue: issue tile 0 into buf 0
    cp16(ksmem + off0, kg + tid);
    cp16(ksmem + off1, kg + tid + 128);
    cp16(vsmem + off0, vg + tid);
    cp16(vsmem + off1, vg + tid + 128);
    asm volatile("cp.async.commit_group;");

    __syncthreads();
    // Q A-fragments (held all kernel)
    u32 qa[8];
    {
        int r = lane & 15, cc = lane >> 4;
        u32 a = (u32)__cvta_generic_to_shared(&Qs[(wrp * 16 + r) * 40 + cc * 8]);
        ldsm_x4(qa + 0, a);
        ldsm_x4(qa + 4, a + 32);
    }

    float o[4][4];
#pragma unroll
    for (int i = 0; i < 4; i++)
#pragma unroll
        for (int j = 0; j < 4; j++) o[i][j] = 0.f;
    float m0 = -1e30f, m1 = -1e30f, l0 = 0.f, l1 = 0.f;

    const u32 kaddr = (u32)__cvta_generic_to_shared(
        &Ks[0][(lane & 7) * 40 + (lane >> 3) * 8]);
    const int vm = lane >> 3;
    const u32 vaddr = (u32)__cvta_generic_to_shared(
        &Vs[0][((vm & 1) * 8 + (lane & 7)) * 40 + (vm >> 1) * 8]);

    for (int t0 = 0; t0 < 4096; t0 += 64) {
        const int buf = (t0 >> 6) & 1;
        const u32 bo = buf * 5120;
        // prefetch next tile into other buffer
        if (t0 + 64 < 4096) {
            const uint4* ks = kg + (t0 + 64) * 4;
            const uint4* vs = vg + (t0 + 64) * 4;
            const u32 nb = (buf ^ 1) * 5120;
            cp16(ksmem + nb + off0, ks + tid);
            cp16(ksmem + nb + off1, ks + tid + 128);
            cp16(vsmem + nb + off0, vs + tid);
            cp16(vsmem + nb + off1, vs + tid + 128);
        }
        asm volatile("cp.async.commit_group;");
        asm volatile("cp.async.wait_group 1;");
        __syncthreads();

        // ---- S = Q K^T
        float s[8][4];
#pragma unroll
        for (int nt = 0; nt < 8; nt++) {
            s[nt][0] = s[nt][1] = s[nt][2] = s[nt][3] = 0.f;
            u32 kb[4];
            ldsm_x4(kb, kaddr + bo + nt * 640);
            mma16816(s[nt], qa + 0, kb + 0);
            mma16816(s[nt], qa + 4, kb + 2);
        }

        // ---- online softmax (base-2, f16x2 exp)
        float mx0 = -1e30f, mx1 = -1e30f;
#pragma unroll
        for (int nt = 0; nt < 8; nt++) {
            mx0 = fmaxf(mx0, fmaxf(s[nt][0], s[nt][1]));
            mx1 = fmaxf(mx1, fmaxf(s[nt][2], s[nt][3]));
        }
        mx0 = fmaxf(mx0, __shfl_xor_sync(0xffffffffu, mx0, 1));
        mx0 = fmaxf(mx0, __shfl_xor_sync(0xffffffffu, mx0, 2));
        mx1 = fmaxf(mx1, __shfl_xor_sync(0xffffffffu, mx1, 1));
        mx1 = fmaxf(mx1, __shfl_xor_sync(0xffffffffu, mx1, 2));
        float nm0 = fmaxf(m0, mx0), nm1 = fmaxf(m1, mx1);
        float corr0 = ex2(m0 - nm0), corr1 = ex2(m1 - nm1);
        m0 = nm0; m1 = nm1;

        u32 pa[8][2];
#pragma unroll
        for (int nt = 0; nt < 8; nt++) {
            pa[nt][0] = ex2h2(packh2(s[nt][0] - m0, s[nt][1] - m0));
            pa[nt][1] = ex2h2(packh2(s[nt][2] - m1, s[nt][3] - m1));
        }
        // l-sums via shallow half2 tree then fp32
        __half2 t00 = __hadd2(__hadd2(u2h(pa[0][0]), u2h(pa[1][0])),
                              __hadd2(u2h(pa[2][0]), u2h(pa[3][0])));
        __half2 t01 = __hadd2(__hadd2(u2h(pa[4][0]), u2h(pa[5][0])),
                              __hadd2(u2h(pa[6][0]), u2h(pa[7][0])));
        __half2 t10 = __hadd2(__hadd2(u2h(pa[0][1]), u2h(pa[1][1])),
                              __hadd2(u2h(pa[2][1]), u2h(pa[3][1])));
        __half2 t11 = __hadd2(__hadd2(u2h(pa[4][1]), u2h(pa[5][1])),
                              __hadd2(u2h(pa[6][1]), u2h(pa[7][1])));
        float2 f0 = __half22float2(__hadd2(t00, t01));
        float2 f1 = __half22float2(__hadd2(t10, t11));
        l0 = l0 * corr0 + f0.x + f0.y;
        l1 = l1 * corr1 + f1.x + f1.y;
#pragma unroll
        for (int nd = 0; nd < 4; nd++) {
            o[nd][0] *= corr0; o[nd][1] *= corr0;
            o[nd][2] *= corr1; o[nd][3] *= corr1;
        }

        // ---- O += P V
#pragma unroll
        for (int kv = 0; kv < 4; kv++) {
            u32 A[4] = {pa[2 * kv][0], pa[2 * kv][1],
                        pa[2 * kv + 1][0], pa[2 * kv + 1][1]};
#pragma unroll
            for (int dh = 0; dh < 2; dh++) {
                u32 vb[4];
                ldsm_x4_t(vb, vaddr + bo + kv * 1280 + dh * 32);
                mma16816(o[2 * dh + 0], A, vb + 0);
                mma16816(o[2 * dh + 1], A, vb + 2);
            }
        }
        __syncthreads();
    }

    // ---- epilogue
    l0 += __shfl_xor_sync(0xffffffffu, l0, 1);
    l0 += __shfl_xor_sync(0xffffffffu, l0, 2);
    l1 += __shfl_xor_sync(0xffffffffu, l1, 1);
    l1 += __shfl_xor_sync(0xffffffffu, l1, 2);
    const float inv0 = 1.f / l0, inv1 = 1.f / l1;
    const int grp = lane >> 2, t4 = lane & 3;
#pragma unroll
    for (int nd = 0; nd < 4; nd++) {
        Os[(wrp * 16 + grp) * 33 + nd * 8 + 2 * t4 + 0] = o[nd][0] * inv0;
        Os[(wrp * 16 + grp) * 33 + nd * 8 + 2 * t4 + 1] = o[nd][1] * inv0;
        Os[(wrp * 16 + grp + 8) * 33 + nd * 8 + 2 * t4 + 0] = o[nd][2] * inv1;
        Os[(wrp * 16 + grp + 8) * 33 + nd * 8 + 2 * t4 + 1] = o[nd][3] * inv1;
    }
    __syncthreads();

    __half* ob = &g_aoh[(long)(b * 128 + hh * 32) * 4096 + q0];
    const int dd = tid >> 2, seg = tid & 3;
    union { __half hx[16]; uint4 ux[2]; } tmp;
#pragma unroll
    for (int i = 0; i < 16; i++)
        tmp.hx[i] = __float2half(Os[(seg * 16 + i) * 33 + dd]);
    uint4* dsth = (uint4*)&ob[dd * 4096 + seg * 16];
    dsth[0] = tmp.ux[0];
    dsth[1] = tmp.ux[1];
}

// ===========================================================================
// Kernel 3: output projection on tensor cores + bias + GN partials.
// grid (64, 2, 4), 128 threads.
// ===========================================================================
__global__ __launch_bounds__(128) void proj_kernel(const float* __restrict__ w,
                                                   const float* __restrict__ bias) {
    __shared__ __align__(16) char smemBuf[17408 + 18432];
    __half* Ws = (__half*)smemBuf;              // [64][136]
    __half* Xs = (__half*)(smemBuf + 17408);    // [128][72]
    float* Osf = (float*)smemBuf;               // overlay [64m][68]
    __shared__ float wred[4][2];

    const int b = blockIdx.z;
    const int n0 = blockIdx.x * 64;
    const int m0 = blockIdx.y * 64;
    const int tid = threadIdx.x;
    const int wrp = tid >> 5, lane = tid & 31;

    for (int idx = tid; idx < 64 * 32; idx += 128) {
        int row = idx >> 5, c4 = idx & 31;
        float4 wv = *(const float4*)&w[(m0 + row) * 128 + c4 * 4];
        *(__half2*)&Ws[row * 136 + c4 * 4 + 0] = __floats2half2_rn(wv.x, wv.y);
        *(__half2*)&Ws[row * 136 + c4 * 4 + 2] = __floats2half2_rn(wv.z, wv.w);
    }
    for (int idx = tid; idx < 128 * 8; idx += 128) {
        int row = idx >> 3, seg = idx & 7;
        *(uint4*)&Xs[row * 72 + seg * 8] =
            *(const uint4*)&g_aoh[(long)(b * 128 + row) * 4096 + n0 + seg * 8];
    }
    __syncthreads();

    float acc[8][4];
#pragma unroll
    for (int i = 0; i < 8; i++)
#pragma unroll
        for (int j = 0; j < 4; j++) acc[i][j] = 0.f;

    const u32 wsAddr = (u32)__cvta_generic_to_shared(
        &Ws[(wrp * 16 + (lane & 15)) * 136 + (lane >> 4) * 8]);
    const int vm = lane >> 3;
    const u32 xsAddr = (u32)__cvta_generic_to_shared(
        &Xs[((vm & 1) * 8 + (lane & 7)) * 72 + (vm >> 1) * 8]);

#pragma unroll
    for (int kk = 0; kk < 8; kk++) {
        u32 wa[4];
        ldsm_x4(wa, wsAddr + kk * 32);
#pragma unroll
        for (int np = 0; np < 4; np++) {
            u32 xb[4];
            ldsm_x4_t(xb, xsAddr + kk * 16 * 144 + np * 32);
            mma16816(acc[2 * np + 0], wa, xb + 0);
            mma16816(acc[2 * np + 1], wa, xb + 2);
        }
    }
    __syncthreads();   // reuse smem as Osf

    const int g = lane >> 2, t4 = lane & 3;
    const int r0 = wrp * 16 + g;
    const float b0 = bias[m0 + r0], b1 = bias[m0 + r0 + 8];
    float lsum = 0.f, lsq = 0.f;
#pragma unroll
    for (int nt = 0; nt < 8; nt++) {
        int col = nt * 8 + 2 * t4;
        float v0 = acc[nt][0] + b0, v1 = acc[nt][1] + b0;
        float v2 = acc[nt][2] + b1, v3 = acc[nt][3] + b1;
        Osf[(r0 + 0) * 68 + col + 0] = v0;
        Osf[(r0 + 0) * 68 + col + 1] = v1;
        Osf[(r0 + 8) * 68 + col + 0] = v2;
        Osf[(r0 + 8) * 68 + col + 1] = v3;
        lsum += (v0 + v1) + (v2 + v3);
        lsq = fmaf(v0, v0, lsq); lsq = fmaf(v1, v1, lsq);
        lsq = fmaf(v2, v2, lsq); lsq = fmaf(v3, v3, lsq);
    }
#pragma unroll
    for (int off = 16; off > 0; off >>= 1) {
        lsum += __shfl_xor_sync(0xffffffffu, lsum, off);
        lsq  += __shfl_xor_sync(0xffffffffu, lsq, off);
    }
    if (lane == 0) { wred[wrp][0] = lsum; wred[wrp][1] = lsq; }
    __syncthreads();
    if (tid == 0) {
        float s0 = wred[0][0] + wred[1][0], q0 = wred[0][1] + wred[1][1];
        float s1 = wred[2][0] + wred[3][0], q1 = wred[2][1] + wred[3][1];
        g_part[((b * 2 + blockIdx.y) * 64 + blockIdx.x) * 2 + 0] = make_float2(s0, q0);
        g_part[((b * 2 + blockIdx.y) * 64 + blockIdx.x) * 2 + 1] = make_float2(s1, q1);
    }

    // coalesced write of y tile
    const int mrow = tid >> 1, seg = tid & 1;
    float* dst = &g_y[(long)(b * 128 + m0 + mrow) * 4096 + n0 + seg * 32];
    const float* src = &Osf[mrow * 68 + seg * 32];
#pragma unroll
    for (int j = 0; j < 8; j++)
        *(float4*)&dst[j * 4] = *(const float4*)&src[j * 4];
}

// ===========================================================================
// Kernel 3b: reduce GN partials. grid (4,4), 64 threads.
// ===========================================================================
__global__ void stats_kernel() {
    const int gg = blockIdx.x, b = blockIdx.y;
    const int by = gg >> 1, gl = gg & 1;
    const int t = threadIdx.x;
    float2 pv = g_part[((b * 2 + by) * 64 + t) * 2 + gl];
    float s = pv.x, ss = pv.y;
#pragma unroll
    for (int off = 16; off > 0; off >>= 1) {
        s  += __shfl_xor_sync(0xffffffffu, s, off);
        ss += __shfl_xor_sync(0xffffffffu, ss, off);
    }
    __shared__ float2 w2[2];
    if ((t & 31) == 0) w2[t >> 5] = make_float2(s, ss);
    __syncthreads();
    if (t == 0) {
        s = w2[0].x + w2[1].x;
        ss = w2[0].y + w2[1].y;
        const float invn = 1.f / 131072.f;
        float mean = s * invn;
        float var = ss * invn - mean * mean;
        g_stats[b * 4 + gg] = make_float2(mean, rsqrtf(var + GN_EPS));
    }
}

// ===========================================================================
// Kernel 4: GroupNorm affine + residual.
// ===========================================================================
__global__ __launch_bounds__(256) void norm_kernel(const float* __restrict__ x,
                                                   const float* __restrict__ gamma,
                                                   const float* __restrict__ beta,
                                                   float* __restrict__ out) {
    const int i4 = blockIdx.x * 256 + threadIdx.x;
    const int e = i4 * 4;
    const int c = (e >> 12) & 127;
    const int b = e >> 19;
    float2 st = g_stats[b * 4 + (c >> 5)];
    float ga = gamma[c] * st.y;
    float be = beta[c] - st.x * ga;
    float4 yv = *(const float4*)&g_y[e];
    float4 xv = *(const float4*)&x[e];
    float4 r;
    r.x = fmaf(yv.x, ga, be) + xv.x;
    r.y = fmaf(yv.y, ga, be) + xv.y;
    r.z = fmaf(yv.z, ga, be) + xv.z;
    r.w = fmaf(yv.w, ga, be) + xv.w;
    *(float4*)&out[e] = r;
}

// ===========================================================================
extern "C" void kernel_launch(void* const* d_in, const int* in_sizes, int n_in,
                              void* d_out, int out_size) {
    const float* x      = (const float*)d_in[0];
    const float* w_qkv  = (const float*)d_in[1];
    const float* w_out  = (const float*)d_in[2];
    const float* b_out  = (const float*)d_in[3];
    const float* gammap = (const float*)d_in[4];
    const float* betap  = (const float*)d_in[5];
    float* out = (float*)d_out;

    cvt_kernel<<<2048, 256>>>(x);
    qkv_kernel<<<dim3(64, 6, 4), 128>>>(w_qkv);
    attn_kernel<<<dim3(64, 4, 4), 128>>>();
    proj_kernel<<<dim3(64, 2, 4), 128>>>(w_out, b_out);
    stats_kernel<<<dim3(4, 4), 64>>>();
    norm_kernel<<<2048, 256>>>(x, gammap, betap, out);
}